// round 4
// baseline (speedup 1.0000x reference)
#include <cuda_runtime.h>
#include <math.h>

#define B_ 128
#define T_ 512
#define F_ 256
#define H_ 512
#define NBLK 128
#define NTHR 256
#define KT 128
#define NTILES (H_ / KT)

// Scratch (device globals: allocation-free per harness rules)
__device__ float g_xproj[(size_t)T_ * H_ * 4 * B_];   // [t][h][g][b], 512 MB
__device__ float g_hT[2][H_ * B_];                     // [parity][h][b]
__device__ volatile unsigned g_arrive;
__device__ volatile unsigned g_release;

// smem layout (floats)
#define SM_RS    0                      // [512][16]  : [k][g*4+c]
#define SM_HS    (SM_RS + H_ * 16)      // [2][KT][128]
#define SM_PRE   (SM_HS + 2 * KT * B_)  // [2][16][132] : [kh][g*4+c][b]
#define SM_XS    (SM_PRE + 2 * 16 * 132)// [4][4][128] : [c][g][b]
#define SM_TOT   (SM_XS + 4 * 4 * B_)

// ---------------------------------------------------------------------------
__global__ void init_kernel() {
    int i = blockIdx.x * blockDim.x + threadIdx.x;
    if (i < H_ * B_) g_hT[0][i] = 0.f;
    if (i == 0) { g_arrive = 0u; g_release = 0u; }
}

// ---------------------------------------------------------------------------
// Input projections: xproj[t][h][g][b] = sum_f x[b][t][f] * Wg[f][h] + bg[h]
// ---------------------------------------------------------------------------
__global__ __launch_bounds__(256) void proj_kernel(
    const float* __restrict__ x,
    const float* __restrict__ W0, const float* __restrict__ b0v,
    const float* __restrict__ W1, const float* __restrict__ b1v,
    const float* __restrict__ W2, const float* __restrict__ b2v,
    const float* __restrict__ W3, const float* __restrict__ b3v)
{
    const int g  = blockIdx.x >> 3;
    const int n0 = (blockIdx.x & 7) * 64;
    const int t  = blockIdx.y >> 1;
    const int b0 = (blockIdx.y & 1) * 64;

    const float* __restrict__ W    = (g == 0) ? W0 : (g == 1) ? W1 : (g == 2) ? W2 : W3;
    const float* __restrict__ bias = (g == 0) ? b0v : (g == 1) ? b1v : (g == 2) ? b2v : b3v;

    __shared__ float As[16][64];
    __shared__ float Bs[16][64];

    const int tid = threadIdx.x;
    const int tx  = tid & 15;
    const int ty  = tid >> 4;

    const int lm  = tid >> 2;
    const int lk4 = (tid & 3) * 4;
    const int wk  = tid >> 4;
    const int wn4 = (tid & 15) * 4;

    float acc[4][4] = {};

    for (int k0 = 0; k0 < F_; k0 += 16) {
        float4 xa = *(const float4*)&x[((size_t)(b0 + lm) * T_ + t) * F_ + k0 + lk4];
        As[lk4 + 0][lm] = xa.x;
        As[lk4 + 1][lm] = xa.y;
        As[lk4 + 2][lm] = xa.z;
        As[lk4 + 3][lm] = xa.w;
        *(float4*)&Bs[wk][wn4] =
            *(const float4*)&W[(size_t)(k0 + wk) * H_ + n0 + wn4];
        __syncthreads();

#pragma unroll
        for (int k = 0; k < 16; k++) {
            float4 a = *(const float4*)&As[k][ty * 4];
            float4 b = *(const float4*)&Bs[k][tx * 4];
            float av[4] = {a.x, a.y, a.z, a.w};
            float bv[4] = {b.x, b.y, b.z, b.w};
#pragma unroll
            for (int i = 0; i < 4; i++)
#pragma unroll
                for (int j = 0; j < 4; j++)
                    acc[i][j] += av[i] * bv[j];
        }
        __syncthreads();
    }

#pragma unroll
    for (int j = 0; j < 4; j++) {
        int h = n0 + tx * 4 + j;
        float bb = bias[h];
        float4 v = make_float4(acc[0][j] + bb, acc[1][j] + bb,
                               acc[2][j] + bb, acc[3][j] + bb);
        *(float4*)&g_xproj[(((size_t)t * H_ + h) * 4 + g) * B_ + b0 + ty * 4] = v;
    }
}

// ---------------------------------------------------------------------------
__device__ __forceinline__ void cpasync16(float* dst_smem, const float4* src) {
    unsigned dst = (unsigned)__cvta_generic_to_shared(dst_smem);
    asm volatile("cp.async.cg.shared.global [%0], [%1], 16;\n"
                 :: "r"(dst), "l"(src));
}

// ---------------------------------------------------------------------------
// Persistent recurrent kernel: 128 blocks x 256 threads, 1 block/SM.
// Block owns 4 h-cols (n0=bid*4), all 4 gates, all 128 batches.
// Split-K: warps 0-3 take the low 64 k of each 128-k tile, warps 4-7 the high.
// ---------------------------------------------------------------------------
__global__ __launch_bounds__(NTHR) void recurrent_kernel(
    const float* __restrict__ Rf, const float* __restrict__ Ri,
    const float* __restrict__ Ro, const float* __restrict__ Rz)
{
    extern __shared__ float smem[];
    float* Rs   = smem + SM_RS;
    float* Hs   = smem + SM_HS;
    float* pre2 = smem + SM_PRE;
    float* xs   = smem + SM_XS;

    const int bid = blockIdx.x;
    const int tid = threadIdx.x;
    const int n0  = bid * 4;

    // Stage R slices once: Rs[k][g*4+c] = Rg[k][n0+c]
    {
        const float* Rm[4] = {Rf, Ri, Ro, Rz};
        for (int idx = tid; idx < H_ * 16; idx += NTHR) {
            int k = idx >> 4;
            int g = (idx >> 2) & 3;
            int c = idx & 3;
            Rs[idx] = Rm[g][(size_t)k * H_ + n0 + c];
        }
    }

    // GEMM thread mapping
    const int kh = tid >> 7;         // k-half within each tile (warps 0-3 / 4-7)
    const int u  = tid & 127;
    const int bq = u >> 2;           // batch quad: b = bq*4..bq*4+3
    const int q  = u & 3;            // gate index (4 cols each)

    // Update thread mapping: 2 elements (col ucol, batches ub, ub+1)
    const int ue   = tid * 2;
    const int ucol = ue >> 7;
    const int ub   = ue & 127;

    float c_reg[2] = {0.f, 0.f};
    float n_reg[2] = {0.f, 0.f};

    // Prefetch xproj[0] into xs (2 x 16B per thread, 8KB total)
    {
        const float4* src = (const float4*)g_xproj;   // t=0, n0 slice below
        const float4* s2  = (const float4*)(g_xproj + (size_t)n0 * 4 * B_);
#pragma unroll
        for (int e = 0; e < 2; e++)
            cpasync16(xs + (e * NTHR + tid) * 4, s2 + e * NTHR + tid);
        (void)src;
        asm volatile("cp.async.commit_group;\n");
    }
    __syncthreads();

    unsigned epoch = 0;

    for (int t = 0; t < T_; t++) {
        const int par = t & 1;
        const float* __restrict__ hsrc = g_hT[par];

        // prefetch k-tile 0 (16 x 16B per thread = 64KB)
        {
            const float4* src = (const float4*)hsrc;
#pragma unroll
            for (int uu = 0; uu < 16; uu++)
                cpasync16(Hs + (uu * NTHR + tid) * 4, src + uu * NTHR + tid);
            asm volatile("cp.async.commit_group;\n");
        }

        float acc[4][4] = {};
        int buf = 0;

        for (int kt = 0; kt < NTILES; kt++) {
            asm volatile("cp.async.wait_group 0;\n");
            __syncthreads();

            if (kt + 1 < NTILES) {
                const float4* src = (const float4*)(hsrc + (kt + 1) * KT * B_);
                float* dstb = Hs + (buf ^ 1) * KT * B_;
#pragma unroll
                for (int uu = 0; uu < 16; uu++)
                    cpasync16(dstb + (uu * NTHR + tid) * 4, src + uu * NTHR + tid);
                asm volatile("cp.async.commit_group;\n");
            }

            // compute this thread's k-half of the tile
            const float* hs_t = Hs + buf * KT * B_ + (kh * 64) * B_ + bq * 4;
            const float* rk   = Rs + (kt * KT + kh * 64) * 16 + q * 4;
#pragma unroll 8
            for (int k = 0; k < 64; k++) {
                float4 a = *(const float4*)(hs_t + k * B_);
                float4 r = *(const float4*)(rk + k * 16);
                acc[0][0] += a.x * r.x;  acc[0][1] += a.x * r.y;
                acc[0][2] += a.x * r.z;  acc[0][3] += a.x * r.w;
                acc[1][0] += a.y * r.x;  acc[1][1] += a.y * r.y;
                acc[1][2] += a.y * r.z;  acc[1][3] += a.y * r.w;
                acc[2][0] += a.z * r.x;  acc[2][1] += a.z * r.y;
                acc[2][2] += a.z * r.z;  acc[2][3] += a.z * r.w;
                acc[3][0] += a.w * r.x;  acc[3][1] += a.w * r.y;
                acc[3][2] += a.w * r.z;  acc[3][3] += a.w * r.w;
            }
            buf ^= 1;
        }

        // write partial preacts: pre2[kh][q*4+j][bq*4+i]
#pragma unroll
        for (int j = 0; j < 4; j++) {
            float4 v = make_float4(acc[0][j], acc[1][j], acc[2][j], acc[3][j]);
            *(float4*)&pre2[(kh * 16 + q * 4 + j) * 132 + bq * 4] = v;
        }
        __syncthreads();

        // ---- pointwise sLSTM update (block-local, xs prefetched) ----
        {
            float2 pf0 = *(const float2*)&pre2[(0 * 16 + 0 * 4 + ucol) * 132 + ub];
            float2 pf1 = *(const float2*)&pre2[(1 * 16 + 0 * 4 + ucol) * 132 + ub];
            float2 pi0 = *(const float2*)&pre2[(0 * 16 + 1 * 4 + ucol) * 132 + ub];
            float2 pi1 = *(const float2*)&pre2[(1 * 16 + 1 * 4 + ucol) * 132 + ub];
            float2 po0 = *(const float2*)&pre2[(0 * 16 + 2 * 4 + ucol) * 132 + ub];
            float2 po1 = *(const float2*)&pre2[(1 * 16 + 2 * 4 + ucol) * 132 + ub];
            float2 pz0 = *(const float2*)&pre2[(0 * 16 + 3 * 4 + ucol) * 132 + ub];
            float2 pz1 = *(const float2*)&pre2[(1 * 16 + 3 * 4 + ucol) * 132 + ub];

            float2 xf = *(const float2*)&xs[(ucol * 4 + 0) * B_ + ub];
            float2 xi = *(const float2*)&xs[(ucol * 4 + 1) * B_ + ub];
            float2 xo = *(const float2*)&xs[(ucol * 4 + 2) * B_ + ub];
            float2 xz = *(const float2*)&xs[(ucol * 4 + 3) * B_ + ub];

            float ftv[2] = {pf0.x + pf1.x + xf.x, pf0.y + pf1.y + xf.y};
            float itv[2] = {pi0.x + pi1.x + xi.x, pi0.y + pi1.y + xi.y};
            float otv[2] = {po0.x + po1.x + xo.x, po0.y + po1.y + xo.y};
            float ztv[2] = {pz0.x + pz1.x + xz.x, pz0.y + pz1.y + xz.y};

            float hv[2];
#pragma unroll
            for (int e = 0; e < 2; e++) {
                float o  = __fdividef(1.f, 1.f + __expf(-otv[e]));
                // tanh(x) = 1 - 2/(exp(2x)+1)
                float z  = 1.f - __fdividef(2.f, __expf(2.f * ztv[e]) + 1.f);
                float fh = __expf(fminf(ftv[e], 10.f));
                float ih = __expf(fminf(itv[e], 10.f));
                float rdn = __fdividef(1.f, fh + ih + 1e-8f);
                float f  = fh * rdn;
                float ii = ih * rdn;
                c_reg[e] = f * c_reg[e] + ii * z;
                n_reg[e] = f * n_reg[e] + ii;
                hv[e] = o * __fdividef(c_reg[e], n_reg[e] + 1e-8f);
            }
            *(float2*)&g_hT[par ^ 1][(n0 + ucol) * B_ + ub] =
                make_float2(hv[0], hv[1]);
        }

        __syncthreads();   // all xs reads done before prefetch overwrites

        // prefetch xproj[t+1] (independent of h) — fills the barrier shadow
        {
            int tn = (t + 1 < T_) ? (t + 1) : t;
            const float4* src =
                (const float4*)(g_xproj + ((size_t)tn * H_ + n0) * 4 * B_);
#pragma unroll
            for (int e = 0; e < 2; e++)
                cpasync16(xs + (e * NTHR + tid) * 4, src + e * NTHR + tid);
            asm volatile("cp.async.commit_group;\n");
        }

        // ---- grid barrier ----
        epoch++;
        if (tid == 0) {
            __threadfence();
            unsigned a = atomicAdd((unsigned*)&g_arrive, 1u) + 1u;
            if (a == epoch * NBLK) {
                g_release = epoch;
                __threadfence();
            } else {
                while (g_release < epoch) __nanosleep(32);
                __threadfence();
            }
        }
        __syncthreads();
    }
}

// ---------------------------------------------------------------------------
__global__ __launch_bounds__(128) void head_kernel(
    const float* __restrict__ fcw, const float* __restrict__ fcb,
    float* __restrict__ out)
{
    int b = blockIdx.x;
    float s = 0.f;
    for (int k = threadIdx.x; k < H_; k += 128)
        s += g_hT[0][(size_t)k * B_ + b] * fcw[k];

    __shared__ float red[4];
#pragma unroll
    for (int off = 16; off; off >>= 1)
        s += __shfl_down_sync(0xffffffff, s, off);
    if ((threadIdx.x & 31) == 0) red[threadIdx.x >> 5] = s;
    __syncthreads();
    if (threadIdx.x == 0) {
        float tot = red[0] + red[1] + red[2] + red[3];
        out[b] = tanhf(tot + fcb[0]);
    }
}

// ---------------------------------------------------------------------------
extern "C" void kernel_launch(void* const* d_in, const int* in_sizes, int n_in,
                              void* d_out, int out_size)
{
    const float* x   = (const float*)d_in[0];
    const float* Wf  = (const float*)d_in[1];
    const float* bf  = (const float*)d_in[2];
    const float* Wi  = (const float*)d_in[3];
    const float* bi  = (const float*)d_in[4];
    const float* Wo  = (const float*)d_in[5];
    const float* bo  = (const float*)d_in[6];
    const float* Wz  = (const float*)d_in[7];
    const float* bz  = (const float*)d_in[8];
    const float* Rf  = (const float*)d_in[9];
    const float* Ri  = (const float*)d_in[10];
    const float* Ro  = (const float*)d_in[11];
    const float* Rz  = (const float*)d_in[12];
    const float* fcw = (const float*)d_in[13];
    const float* fcb = (const float*)d_in[14];
    float* out = (float*)d_out;

    const int smem_bytes = SM_TOT * sizeof(float);
    cudaFuncSetAttribute(recurrent_kernel,
                         cudaFuncAttributeMaxDynamicSharedMemorySize, smem_bytes);

    init_kernel<<<(H_ * B_ + 255) / 256, 256>>>();

    dim3 gA(32, T_ * 2);
    proj_kernel<<<gA, 256>>>(x, Wf, bf, Wi, bi, Wo, bo, Wz, bz);

    recurrent_kernel<<<NBLK, NTHR, smem_bytes>>>(Rf, Ri, Ro, Rz);

    head_kernel<<<B_, 128>>>(fcw, fcb, out);
}

// round 6
// speedup vs baseline: 1.4194x; 1.4194x over previous
#include <cuda_runtime.h>
#include <math.h>

#define B_ 128
#define T_ 512
#define F_ 256
#define H_ 512
#define NBLK 128
#define NTHR 256
#define KT 64
#define NTILES (H_ / KT)

// Scratch (device globals: allocation-free per harness rules)
__device__ float g_xproj[(size_t)T_ * H_ * 4 * B_];   // [t][h][g][b], 512 MB
__device__ float g_hT[2][H_ * B_];                     // [parity][h][b]
__device__ volatile unsigned g_arrive;
__device__ volatile unsigned g_release;

// smem layout (floats)
#define SM_RS   0                        // [512][16]  : [k][g*4+c]
#define SM_HS   (SM_RS + H_ * 16)        // [2][KT][128]
#define SM_PRE  (SM_HS + 2 * KT * B_)    // [16][132]  : [g*4+c][b]
#define SM_XS   (SM_PRE + 16 * 132)      // [4][4][128]: [c][g][b]
#define SM_TOT  (SM_XS + 4 * 4 * B_)

// ---------------------------------------------------------------------------
__global__ void init_kernel() {
    int i = blockIdx.x * blockDim.x + threadIdx.x;
    if (i < H_ * B_) g_hT[0][i] = 0.f;
    if (i == 0) { g_arrive = 0u; g_release = 0u; }
}

// ---------------------------------------------------------------------------
// Input projections: xproj[t][h][g][b] = sum_f x[b][t][f] * Wg[f][h] + bg[h]
// ---------------------------------------------------------------------------
__global__ __launch_bounds__(256) void proj_kernel(
    const float* __restrict__ x,
    const float* __restrict__ W0, const float* __restrict__ b0v,
    const float* __restrict__ W1, const float* __restrict__ b1v,
    const float* __restrict__ W2, const float* __restrict__ b2v,
    const float* __restrict__ W3, const float* __restrict__ b3v)
{
    const int g  = blockIdx.x >> 3;
    const int n0 = (blockIdx.x & 7) * 64;
    const int t  = blockIdx.y >> 1;
    const int b0 = (blockIdx.y & 1) * 64;

    const float* __restrict__ W    = (g == 0) ? W0 : (g == 1) ? W1 : (g == 2) ? W2 : W3;
    const float* __restrict__ bias = (g == 0) ? b0v : (g == 1) ? b1v : (g == 2) ? b2v : b3v;

    __shared__ float As[16][64];
    __shared__ float Bs[16][64];

    const int tid = threadIdx.x;
    const int tx  = tid & 15;
    const int ty  = tid >> 4;

    const int lm  = tid >> 2;
    const int lk4 = (tid & 3) * 4;
    const int wk  = tid >> 4;
    const int wn4 = (tid & 15) * 4;

    float acc[4][4] = {};

    for (int k0 = 0; k0 < F_; k0 += 16) {
        float4 xa = *(const float4*)&x[((size_t)(b0 + lm) * T_ + t) * F_ + k0 + lk4];
        As[lk4 + 0][lm] = xa.x;
        As[lk4 + 1][lm] = xa.y;
        As[lk4 + 2][lm] = xa.z;
        As[lk4 + 3][lm] = xa.w;
        *(float4*)&Bs[wk][wn4] =
            *(const float4*)&W[(size_t)(k0 + wk) * H_ + n0 + wn4];
        __syncthreads();

#pragma unroll
        for (int k = 0; k < 16; k++) {
            float4 a = *(const float4*)&As[k][ty * 4];
            float4 b = *(const float4*)&Bs[k][tx * 4];
            float av[4] = {a.x, a.y, a.z, a.w};
            float bv[4] = {b.x, b.y, b.z, b.w};
#pragma unroll
            for (int i = 0; i < 4; i++)
#pragma unroll
                for (int j = 0; j < 4; j++)
                    acc[i][j] += av[i] * bv[j];
        }
        __syncthreads();
    }

#pragma unroll
    for (int j = 0; j < 4; j++) {
        int h = n0 + tx * 4 + j;
        float bb = bias[h];
        float4 v = make_float4(acc[0][j] + bb, acc[1][j] + bb,
                               acc[2][j] + bb, acc[3][j] + bb);
        *(float4*)&g_xproj[(((size_t)t * H_ + h) * 4 + g) * B_ + b0 + ty * 4] = v;
    }
}

// ---------------------------------------------------------------------------
__device__ __forceinline__ void cpasync16(float* dst_smem, const float4* src) {
    unsigned dst = (unsigned)__cvta_generic_to_shared(dst_smem);
    asm volatile("cp.async.cg.shared.global [%0], [%1], 16;\n"
                 :: "r"(dst), "l"(src));
}

// ---------------------------------------------------------------------------
// Persistent recurrent kernel: 128 blocks x 256 threads, 1 block/SM.
// Block owns 4 h-cols (n0=bid*4), all 4 gates, all 128 batches.
// (Exact R3 GEMM structure: KT=64, 8 tiles, 4x2 register tile.)
// ---------------------------------------------------------------------------
__global__ __launch_bounds__(NTHR) void recurrent_kernel(
    const float* __restrict__ Rf, const float* __restrict__ Ri,
    const float* __restrict__ Ro, const float* __restrict__ Rz)
{
    extern __shared__ float smem[];
    float* Rs  = smem + SM_RS;
    float* Hs  = smem + SM_HS;
    float* pre = smem + SM_PRE;
    float* xs  = smem + SM_XS;

    const int bid = blockIdx.x;
    const int tid = threadIdx.x;
    const int n0  = bid * 4;

    // Stage R slices once: Rs[k][g*4+c] = Rg[k][n0+c]
    {
        const float* Rm[4] = {Rf, Ri, Ro, Rz};
        for (int idx = tid; idx < H_ * 16; idx += NTHR) {
            int k = idx >> 4;
            int g = (idx >> 2) & 3;
            int c = idx & 3;
            Rs[idx] = Rm[g][(size_t)k * H_ + n0 + c];
        }
    }

    // GEMM thread mapping (R3)
    const int p  = tid & 1;          // col pair: cols p*2, p*2+1
    const int g  = (tid >> 1) & 3;   // gate
    const int bq = tid >> 3;         // batch quad: b = bq*4..bq*4+3
    const float* rs_t = Rs + g * 4 + p * 2;

    // Update thread mapping: 2 elements (col ucol, batches ub, ub+1)
    const int ue   = tid * 2;
    const int ucol = ue >> 7;
    const int ub   = ue & 127;

    float c_reg[2] = {0.f, 0.f};
    float n_reg[2] = {0.f, 0.f};

    // Prefetch xproj[0] into xs (8KB: 2 x float4 per thread)
    {
        const float4* src = (const float4*)(g_xproj + (size_t)n0 * 4 * B_);
#pragma unroll
        for (int e = 0; e < 2; e++)
            cpasync16(xs + (e * NTHR + tid) * 4, src + e * NTHR + tid);
        asm volatile("cp.async.commit_group;\n");
    }
    __syncthreads();

    unsigned epoch = 0;

    for (int t = 0; t < T_; t++) {
        const int par = t & 1;
        const float* __restrict__ hsrc = g_hT[par];

        // prefetch k-tile 0 (8 x 16B per thread = 32KB)
        {
            const float4* src = (const float4*)hsrc;
#pragma unroll
            for (int u = 0; u < 8; u++)
                cpasync16(Hs + (u * NTHR + tid) * 4, src + u * NTHR + tid);
            asm volatile("cp.async.commit_group;\n");
        }

        float acc[4][2] = {};
        int buf = 0;

        for (int kt = 0; kt < NTILES; kt++) {
            asm volatile("cp.async.wait_group 0;\n");
            __syncthreads();

            if (kt + 1 < NTILES) {
                const float4* src = (const float4*)(hsrc + (kt + 1) * KT * B_);
                float* dstb = Hs + (buf ^ 1) * KT * B_;
#pragma unroll
                for (int u = 0; u < 8; u++)
                    cpasync16(dstb + (u * NTHR + tid) * 4, src + u * NTHR + tid);
                asm volatile("cp.async.commit_group;\n");
            }

            const float* hs_t = Hs + buf * KT * B_ + bq * 4;
            const float* rk   = rs_t + kt * KT * 16;
#pragma unroll 8
            for (int k = 0; k < KT; k++) {
                float4 a = *(const float4*)(hs_t + k * B_);
                float2 r = *(const float2*)(rk + k * 16);
                acc[0][0] += a.x * r.x;  acc[0][1] += a.x * r.y;
                acc[1][0] += a.y * r.x;  acc[1][1] += a.y * r.y;
                acc[2][0] += a.z * r.x;  acc[2][1] += a.z * r.y;
                acc[3][0] += a.w * r.x;  acc[3][1] += a.w * r.y;
            }
            buf ^= 1;
        }

        // write preacts to smem
#pragma unroll
        for (int j = 0; j < 2; j++)
#pragma unroll
            for (int i = 0; i < 4; i++)
                pre[(g * 4 + p * 2 + j) * 132 + bq * 4 + i] = acc[i][j];
        __syncthreads();

        // ---- pointwise sLSTM update (block-local, xs prefetched) ----
        {
            float2 hrf = *(const float2*)&pre[(0 * 4 + ucol) * 132 + ub];
            float2 hri = *(const float2*)&pre[(1 * 4 + ucol) * 132 + ub];
            float2 hro = *(const float2*)&pre[(2 * 4 + ucol) * 132 + ub];
            float2 hrz = *(const float2*)&pre[(3 * 4 + ucol) * 132 + ub];

            float2 xf = *(const float2*)&xs[(ucol * 4 + 0) * B_ + ub];
            float2 xi = *(const float2*)&xs[(ucol * 4 + 1) * B_ + ub];
            float2 xo = *(const float2*)&xs[(ucol * 4 + 2) * B_ + ub];
            float2 xz = *(const float2*)&xs[(ucol * 4 + 3) * B_ + ub];

            float ftv[2] = {hrf.x + xf.x, hrf.y + xf.y};
            float itv[2] = {hri.x + xi.x, hri.y + xi.y};
            float otv[2] = {hro.x + xo.x, hro.y + xo.y};
            float ztv[2] = {hrz.x + xz.x, hrz.y + xz.y};

            float hv[2];
#pragma unroll
            for (int e = 0; e < 2; e++) {
                float o  = __fdividef(1.f, 1.f + __expf(-otv[e]));
                float z  = 1.f - __fdividef(2.f, __expf(2.f * ztv[e]) + 1.f);
                float fh = __expf(fminf(ftv[e], 10.f));
                float ih = __expf(fminf(itv[e], 10.f));
                float rdn = __fdividef(1.f, fh + ih + 1e-8f);
                float f  = fh * rdn;
                float ii = ih * rdn;
                c_reg[e] = f * c_reg[e] + ii * z;
                n_reg[e] = f * n_reg[e] + ii;
                hv[e] = o * __fdividef(c_reg[e], n_reg[e] + 1e-8f);
            }
            *(float2*)&g_hT[par ^ 1][(n0 + ucol) * B_ + ub] =
                make_float2(hv[0], hv[1]);
        }

        __syncthreads();   // all xs reads done before prefetch overwrites

        // prefetch xproj[t+1] (h-independent) — fills the barrier shadow
        {
            int tn = (t + 1 < T_) ? (t + 1) : t;
            const float4* src =
                (const float4*)(g_xproj + ((size_t)tn * H_ + n0) * 4 * B_);
#pragma unroll
            for (int e = 0; e < 2; e++)
                cpasync16(xs + (e * NTHR + tid) * 4, src + e * NTHR + tid);
            asm volatile("cp.async.commit_group;\n");
        }

        // ---- grid barrier (plain spin, no nanosleep) ----
        epoch++;
        if (tid == 0) {
            __threadfence();
            unsigned a = atomicAdd((unsigned*)&g_arrive, 1u) + 1u;
            if (a == epoch * NBLK) {
                g_release = epoch;
                __threadfence();
            } else {
                while (g_release < epoch) { }
                __threadfence();
            }
        }
        __syncthreads();
    }
}

// ---------------------------------------------------------------------------
__global__ __launch_bounds__(128) void head_kernel(
    const float* __restrict__ fcw, const float* __restrict__ fcb,
    float* __restrict__ out)
{
    int b = blockIdx.x;
    float s = 0.f;
    for (int k = threadIdx.x; k < H_; k += 128)
        s += g_hT[0][(size_t)k * B_ + b] * fcw[k];

    __shared__ float red[4];
#pragma unroll
    for (int off = 16; off; off >>= 1)
        s += __shfl_down_sync(0xffffffff, s, off);
    if ((threadIdx.x & 31) == 0) red[threadIdx.x >> 5] = s;
    __syncthreads();
    if (threadIdx.x == 0) {
        float tot = red[0] + red[1] + red[2] + red[3];
        out[b] = tanhf(tot + fcb[0]);
    }
}

// ---------------------------------------------------------------------------
extern "C" void kernel_launch(void* const* d_in, const int* in_sizes, int n_in,
                              void* d_out, int out_size)
{
    const float* x   = (const float*)d_in[0];
    const float* Wf  = (const float*)d_in[1];
    const float* bf  = (const float*)d_in[2];
    const float* Wi  = (const float*)d_in[3];
    const float* bi  = (const float*)d_in[4];
    const float* Wo  = (const float*)d_in[5];
    const float* bo  = (const float*)d_in[6];
    const float* Wz  = (const float*)d_in[7];
    const float* bz  = (const float*)d_in[8];
    const float* Rf  = (const float*)d_in[9];
    const float* Ri  = (const float*)d_in[10];
    const float* Ro  = (const float*)d_in[11];
    const float* Rz  = (const float*)d_in[12];
    const float* fcw = (const float*)d_in[13];
    const float* fcb = (const float*)d_in[14];
    float* out = (float*)d_out;

    const int smem_bytes = SM_TOT * sizeof(float);
    cudaFuncSetAttribute(recurrent_kernel,
                         cudaFuncAttributeMaxDynamicSharedMemorySize, smem_bytes);

    init_kernel<<<(H_ * B_ + 255) / 256, 256>>>();

    dim3 gA(32, T_ * 2);
    proj_kernel<<<gA, 256>>>(x, Wf, bf, Wi, bi, Wo, bo, Wz, bz);

    recurrent_kernel<<<NBLK, NTHR, smem_bytes>>>(Rf, Ri, Ro, Rz);

    head_kernel<<<B_, 128>>>(fcw, fcb, out);
}

// round 8
// speedup vs baseline: 2.3980x; 1.6895x over previous
#include <cuda_runtime.h>
#include <cuda_bf16.h>
#include <math.h>
#include <stdint.h>

#define B_ 128
#define T_ 512
#define F_ 256
#define H_ 512
#define NBLK 128
#define NTHR 256
#define KC 64                 // K per streamed chunk
#define NCHUNK (H_ / KC)      // 8

// ---------------- device globals (allocation-free scratch) ------------------
__device__ float g_xproj[(size_t)T_ * H_ * 4 * B_];        // [t][h][g][b]
__device__ __nv_bfloat16 g_hbf[2][2][B_][H_];              // [parity][hi/lo][b][k]
__device__ volatile unsigned g_arrive;
__device__ volatile unsigned g_release;

// ---------------- smem byte offsets (dynamic) -------------------------------
#define SMB_A    0            // [2 buf][2 hl][16384] = 65536 (A chunks, SW128 rows of 128B)
#define SMB_B    65536        // [2 hl][16 n][1024]   = 32768 (B^T, XOR-swizzled rows)
#define SMB_XS   98304        // float[4c][4g][128b]  = 8192
#define SMB_PRE  106496       // float[16][132]       = 8448
#define SMB_TOT  114944

// ---------------------------------------------------------------------------
__device__ __forceinline__ uint32_t smem_u32(const void* p) {
    uint32_t a;
    asm("{ .reg .u64 t; cvta.to.shared.u64 t, %1; cvt.u32.u64 %0, t; }" : "=r"(a) : "l"(p));
    return a;
}

__device__ __forceinline__ void cpasync16(uint32_t dst_smem, const void* src) {
    asm volatile("cp.async.cg.shared.global [%0], [%1], 16;\n"
                 :: "r"(dst_smem), "l"(src));
}

__device__ __forceinline__ void ldsm4(uint32_t* r, uint32_t addr) {
    asm volatile("ldmatrix.sync.aligned.m8n8.x4.shared.b16 {%0,%1,%2,%3}, [%4];"
                 : "=r"(r[0]), "=r"(r[1]), "=r"(r[2]), "=r"(r[3]) : "r"(addr));
}

__device__ __forceinline__ void mma16816(float* d, const uint32_t* a,
                                         uint32_t b0, uint32_t b1) {
    asm volatile(
        "mma.sync.aligned.m16n8k16.row.col.f32.bf16.bf16.f32 "
        "{%0,%1,%2,%3}, {%4,%5,%6,%7}, {%8,%9}, {%0,%1,%2,%3};"
        : "+f"(d[0]), "+f"(d[1]), "+f"(d[2]), "+f"(d[3])
        : "r"(a[0]), "r"(a[1]), "r"(a[2]), "r"(a[3]), "r"(b0), "r"(b1));
}

// ---------------------------------------------------------------------------
__global__ void init_kernel() {
    int i = blockIdx.x * blockDim.x + threadIdx.x;
    if (i < 2 * B_ * H_) ((__nv_bfloat16*)g_hbf[0])[i] = __float2bfloat16(0.f);
    if (i == 0) { g_arrive = 0u; g_release = 0u; }
}

// ---------------------------------------------------------------------------
// Input projections: xproj[t][h][g][b] = sum_f x[b][t][f] * Wg[f][h] + bg[h]
// ---------------------------------------------------------------------------
__global__ __launch_bounds__(256) void proj_kernel(
    const float* __restrict__ x,
    const float* __restrict__ W0, const float* __restrict__ b0v,
    const float* __restrict__ W1, const float* __restrict__ b1v,
    const float* __restrict__ W2, const float* __restrict__ b2v,
    const float* __restrict__ W3, const float* __restrict__ b3v)
{
    const int g  = blockIdx.x >> 3;
    const int n0 = (blockIdx.x & 7) * 64;
    const int t  = blockIdx.y >> 1;
    const int b0 = (blockIdx.y & 1) * 64;

    const float* __restrict__ W    = (g == 0) ? W0 : (g == 1) ? W1 : (g == 2) ? W2 : W3;
    const float* __restrict__ bias = (g == 0) ? b0v : (g == 1) ? b1v : (g == 2) ? b2v : b3v;

    __shared__ float As[16][64];
    __shared__ float Bs[16][64];

    const int tid = threadIdx.x;
    const int tx  = tid & 15;
    const int ty  = tid >> 4;

    const int lm  = tid >> 2;
    const int lk4 = (tid & 3) * 4;
    const int wk  = tid >> 4;
    const int wn4 = (tid & 15) * 4;

    float acc[4][4] = {};

    for (int k0 = 0; k0 < F_; k0 += 16) {
        float4 xa = *(const float4*)&x[((size_t)(b0 + lm) * T_ + t) * F_ + k0 + lk4];
        As[lk4 + 0][lm] = xa.x;
        As[lk4 + 1][lm] = xa.y;
        As[lk4 + 2][lm] = xa.z;
        As[lk4 + 3][lm] = xa.w;
        *(float4*)&Bs[wk][wn4] =
            *(const float4*)&W[(size_t)(k0 + wk) * H_ + n0 + wn4];
        __syncthreads();

#pragma unroll
        for (int k = 0; k < 16; k++) {
            float4 a = *(const float4*)&As[k][ty * 4];
            float4 b = *(const float4*)&Bs[k][tx * 4];
            float av[4] = {a.x, a.y, a.z, a.w};
            float bv[4] = {b.x, b.y, b.z, b.w};
#pragma unroll
            for (int i = 0; i < 4; i++)
#pragma unroll
                for (int j = 0; j < 4; j++)
                    acc[i][j] += av[i] * bv[j];
        }
        __syncthreads();
    }

#pragma unroll
    for (int j = 0; j < 4; j++) {
        int h = n0 + tx * 4 + j;
        float bb = bias[h];
        float4 v = make_float4(acc[0][j] + bb, acc[1][j] + bb,
                               acc[2][j] + bb, acc[3][j] + bb);
        *(float4*)&g_xproj[(((size_t)t * H_ + h) * 4 + g) * B_ + b0 + ty * 4] = v;
    }
}

// ---------------------------------------------------------------------------
// Persistent recurrent kernel: 128 blocks x 256 threads (8 warps), 1/SM.
// Block owns N=16 cols (4 h-cols x 4 gates, n = g*4+c), M=128 batches, K=512.
// D = Ahi*Bhi + Ahi*Blo + Alo*Bhi via mma.sync m16n8k16 bf16 (fp32 accum).
// Warp w owns m-rows [w*16, w*16+16); both n-tiles (n 0-7, 8-15).
// ---------------------------------------------------------------------------
__global__ __launch_bounds__(NTHR) void recurrent_kernel(
    const float* __restrict__ Rf, const float* __restrict__ Ri,
    const float* __restrict__ Ro, const float* __restrict__ Rz)
{
    extern __shared__ __align__(1024) char smem[];
    const uint32_t sb = smem_u32(smem);

    const int bid  = blockIdx.x;
    const int tid  = threadIdx.x;
    const int w    = tid >> 5;
    const int lane = tid & 31;
    const int n0   = bid * 4;

    float* xsf = (float*)(smem + SMB_XS);
    float* pre = (float*)(smem + SMB_PRE);

    // ---- stage split R^T into smem (once): row n = g*4+c, 512 k, swizzled ----
    {
        const float* Rm[4] = {Rf, Ri, Ro, Rz};
        for (int idx = tid; idx < 16 * H_; idx += NTHR) {
            int n = idx & 15;
            int k = idx >> 4;
            int gg = n >> 2, c = n & 3;
            float v = Rm[gg][(size_t)k * H_ + n0 + c];
            __nv_bfloat16 vhi = __float2bfloat16(v);
            __nv_bfloat16 vlo = __float2bfloat16(v - __bfloat162float(vhi));
            uint32_t u = k >> 3;
            uint32_t off = n * 1024 + ((u ^ (n & 7)) << 4) + (k & 7) * 2;
            *(__nv_bfloat16*)(smem + SMB_B + off) = vhi;
            *(__nv_bfloat16*)(smem + SMB_B + 16384 + off) = vlo;
        }
    }

    // ---- prefetch xproj[0] (8KB: 2 x 16B per thread) ----
    {
        const float4* src = (const float4*)(g_xproj + (size_t)n0 * 4 * B_);
#pragma unroll
        for (int e = 0; e < 2; e++)
            cpasync16(sb + SMB_XS + (e * NTHR + tid) * 16, src + e * NTHR + tid);
        asm volatile("cp.async.commit_group;\n");
    }
    __syncthreads();

    // ldmatrix row addressing: row = base + (lane&15), k-unit += (lane>>4)
    const int lrow = lane & 15;
    const int lku  = lane >> 4;
    const uint32_t a_base = sb + SMB_A + (w * 16 + lrow) * 128;
    const uint32_t a_sw   = (w * 16 + lrow) & 7;
    const uint32_t b_base = sb + SMB_B + lrow * 1024;
    const uint32_t b_sw   = lrow & 7;

    // update-phase mapping: thread -> (batch b, col pair)
    const int ub  = tid & 127;
    const int ucp = tid >> 7;        // cols ucp*2, ucp*2+1
    float c_reg[2] = {0.f, 0.f};
    float n_reg[2] = {0.f, 0.f};

    unsigned epoch = 0;

    for (int t = 0; t < T_; t++) {
        const int par = t & 1;
        const __nv_bfloat16* __restrict__ hsrc = &g_hbf[par][0][0][0];

        // ---- load chunk 0 into buf 0 (32KB: hi+lo, 8 x 16B per thread) ----
        {
#pragma unroll
            for (int i = 0; i < 8; i++) {
                int lin = i * NTHR + tid;      // 0..2047
                int hl = lin >> 10;
                int r  = lin & 1023;
                int m  = r >> 3;
                int s  = r & 7;
                const __nv_bfloat16* src = hsrc + ((size_t)hl * B_ + m) * H_ + s * 8;
                cpasync16(sb + SMB_A + hl * 16384 + m * 128 + ((s ^ (m & 7)) << 4), src);
            }
            asm volatile("cp.async.commit_group;\n");
        }

        float acc[2][4] = {};

        for (int kt = 0; kt < NCHUNK; kt++) {
            const int buf = kt & 1;

            if (kt + 1 < NCHUNK) {
                asm volatile("cp.async.wait_group 0;\n" ::: "memory");
                __syncthreads();
                const int nbuf = buf ^ 1;
#pragma unroll
                for (int i = 0; i < 8; i++) {
                    int lin = i * NTHR + tid;
                    int hl = lin >> 10;
                    int r  = lin & 1023;
                    int m  = r >> 3;
                    int s  = r & 7;
                    const __nv_bfloat16* src =
                        hsrc + ((size_t)hl * B_ + m) * H_ + (kt + 1) * KC + s * 8;
                    cpasync16(sb + SMB_A + nbuf * 32768 + hl * 16384 +
                              m * 128 + ((s ^ (m & 7)) << 4), src);
                }
                asm volatile("cp.async.commit_group;\n");
            } else {
                asm volatile("cp.async.wait_group 0;\n" ::: "memory");
                __syncthreads();
            }

            const uint32_t abuf = a_base + buf * 32768;
#pragma unroll
            for (int j = 0; j < 4; j++) {           // 4 k-tiles of 16
                uint32_t au = (uint32_t)(j * 2 + lku);
                uint32_t bu = (uint32_t)(kt * 8 + j * 2 + lku);
                uint32_t a_hi = abuf + ((au ^ a_sw) << 4);
                uint32_t a_lo = a_hi + 16384;
                uint32_t b_hi = b_base + ((bu ^ b_sw) << 4);
                uint32_t b_lo = b_hi + 16384;

                uint32_t ah[4], al[4], bh[4], bl[4];
                ldsm4(ah, a_hi);
                ldsm4(al, a_lo);
                ldsm4(bh, b_hi);
                ldsm4(bl, b_lo);

                // ntile0 uses {r0,r2}; ntile1 uses {r1,r3}
                mma16816(acc[0], ah, bh[0], bh[2]);
                mma16816(acc[0], ah, bl[0], bl[2]);
                mma16816(acc[0], al, bh[0], bh[2]);
                mma16816(acc[1], ah, bh[1], bh[3]);
                mma16816(acc[1], ah, bl[1], bl[3]);
                mma16816(acc[1], al, bh[1], bh[3]);
            }
        }

        // ---- epilogue: D fragments -> pre[n][m] (stride 132, conflict-free) ----
        {
            int row0 = w * 16 + (lane >> 2);
#pragma unroll
            for (int nt = 0; nt < 2; nt++) {
                int col0 = nt * 8 + (lane & 3) * 2;
                pre[(col0    ) * 132 + row0    ] = acc[nt][0];
                pre[(col0 + 1) * 132 + row0    ] = acc[nt][1];
                pre[(col0    ) * 132 + row0 + 8] = acc[nt][2];
                pre[(col0 + 1) * 132 + row0 + 8] = acc[nt][3];
            }
        }
        __syncthreads();

        // ---- pointwise sLSTM update (thread-local c/n) ----
        {
            const int np = par ^ 1;
            uint32_t phi, plo;
            __nv_bfloat16* vhi = (__nv_bfloat16*)&phi;
            __nv_bfloat16* vlo = (__nv_bfloat16*)&plo;
#pragma unroll
            for (int e = 0; e < 2; e++) {
                int c = ucp * 2 + e;
                float ft = pre[(0 * 4 + c) * 132 + ub] + xsf[(c * 4 + 0) * B_ + ub];
                float it = pre[(1 * 4 + c) * 132 + ub] + xsf[(c * 4 + 1) * B_ + ub];
                float ot = pre[(2 * 4 + c) * 132 + ub] + xsf[(c * 4 + 2) * B_ + ub];
                float zt = pre[(3 * 4 + c) * 132 + ub] + xsf[(c * 4 + 3) * B_ + ub];

                float o  = __fdividef(1.f, 1.f + __expf(-ot));
                float z  = 1.f - __fdividef(2.f, __expf(2.f * zt) + 1.f);
                float fh = __expf(fminf(ft, 10.f));
                float ih = __expf(fminf(it, 10.f));
                float rd = __fdividef(1.f, fh + ih + 1e-8f);
                float f  = fh * rd;
                float ii = ih * rd;
                c_reg[e] = f * c_reg[e] + ii * z;
                n_reg[e] = f * n_reg[e] + ii;
                float hv = o * __fdividef(c_reg[e], n_reg[e] + 1e-8f);

                vhi[e] = __float2bfloat16(hv);
                vlo[e] = __float2bfloat16(hv - __bfloat162float(vhi[e]));
            }
            *(uint32_t*)&g_hbf[np][0][ub][n0 + ucp * 2] = phi;
            *(uint32_t*)&g_hbf[np][1][ub][n0 + ucp * 2] = plo;
        }

        __syncthreads();   // xs/pre reads done before reuse

        // ---- prefetch xproj[t+1] in the barrier shadow ----
        {
            int tn = (t + 1 < T_) ? (t + 1) : t;
            const float4* src =
                (const float4*)(g_xproj + ((size_t)tn * H_ + n0) * 4 * B_);
#pragma unroll
            for (int e = 0; e < 2; e++)
                cpasync16(sb + SMB_XS + (e * NTHR + tid) * 16, src + e * NTHR + tid);
            asm volatile("cp.async.commit_group;\n");
        }

        // ---- grid barrier ----
        epoch++;
        if (tid == 0) {
            __threadfence();
            unsigned a = atomicAdd((unsigned*)&g_arrive, 1u) + 1u;
            if (a == epoch * NBLK) {
                g_release = epoch;
                __threadfence();
            } else {
                while (g_release < epoch) { }
                __threadfence();
            }
        }
        __syncthreads();
    }

    asm volatile("cp.async.wait_group 0;\n" ::: "memory");
}

// ---------------------------------------------------------------------------
__global__ __launch_bounds__(128) void head_kernel(
    const float* __restrict__ fcw, const float* __restrict__ fcb,
    float* __restrict__ out)
{
    int b = blockIdx.x;
    float s = 0.f;
    for (int k = threadIdx.x; k < H_; k += 128) {
        float hv = __bfloat162float(g_hbf[0][0][b][k]) +
                   __bfloat162float(g_hbf[0][1][b][k]);
        s += hv * fcw[k];
    }

    __shared__ float red[4];
#pragma unroll
    for (int off = 16; off; off >>= 1)
        s += __shfl_down_sync(0xffffffff, s, off);
    if ((threadIdx.x & 31) == 0) red[threadIdx.x >> 5] = s;
    __syncthreads();
    if (threadIdx.x == 0) {
        float tot = red[0] + red[1] + red[2] + red[3];
        out[b] = tanhf(tot + fcb[0]);
    }
}

// ---------------------------------------------------------------------------
extern "C" void kernel_launch(void* const* d_in, const int* in_sizes, int n_in,
                              void* d_out, int out_size)
{
    const float* x   = (const float*)d_in[0];
    const float* Wf  = (const float*)d_in[1];
    const float* bf  = (const float*)d_in[2];
    const float* Wi  = (const float*)d_in[3];
    const float* bi  = (const float*)d_in[4];
    const float* Wo  = (const float*)d_in[5];
    const float* bo  = (const float*)d_in[6];
    const float* Wz  = (const float*)d_in[7];
    const float* bz  = (const float*)d_in[8];
    const float* Rf  = (const float*)d_in[9];
    const float* Ri  = (const float*)d_in[10];
    const float* Ro  = (const float*)d_in[11];
    const float* Rz  = (const float*)d_in[12];
    const float* fcw = (const float*)d_in[13];
    const float* fcb = (const float*)d_in[14];
    float* out = (float*)d_out;

    cudaFuncSetAttribute(recurrent_kernel,
                         cudaFuncAttributeMaxDynamicSharedMemorySize, SMB_TOT);

    init_kernel<<<(2 * B_ * H_ + 255) / 256, 256>>>();

    dim3 gA(32, T_ * 2);
    proj_kernel<<<gA, 256>>>(x, Wf, bf, Wi, bi, Wo, bo, Wz, bz);

    recurrent_kernel<<<NBLK, NTHR, SMB_TOT>>>(Rf, Ri, Ro, Rz);

    head_kernel<<<B_, 128>>>(fcw, fcb, out);
}

// round 9
// speedup vs baseline: 3.2802x; 1.3679x over previous
#include <cuda_runtime.h>
#include <cuda_bf16.h>
#include <math.h>
#include <stdint.h>

#define B_ 128
#define T_ 512
#define F_ 256
#define H_ 512
#define NG 2048               // H_*4 fused gate cols, n = h*4+g
#define NBLK 128
#define NTHR 256
#define KC 64
#define NCHUNK (H_ / KC)      // 8

// ---------------- device globals (allocation-free scratch) ------------------
__device__ float g_xproj[(size_t)T_ * B_ * NG];            // [t][b][n], row = t*128+b
__device__ unsigned char g_xs[2][(size_t)B_ * T_ * F_ * 2]; // bf16 hi/lo, pre-swizzled 512B rows
__device__ unsigned char g_wt[2][(size_t)NG * F_ * 2];      // bf16 hi/lo W^T, pre-swizzled
__device__ float g_bc[NG];                                  // fused bias
__device__ __nv_bfloat16 g_hbf[2][2][B_][H_];               // [parity][hi/lo][b][k]
__device__ volatile unsigned g_arrive;
__device__ volatile unsigned g_release;

// ---------------------------------------------------------------------------
__device__ __forceinline__ uint32_t smem_u32(const void* p) {
    uint32_t a;
    asm("{ .reg .u64 t; cvta.to.shared.u64 t, %1; cvt.u32.u64 %0, t; }" : "=r"(a) : "l"(p));
    return a;
}
__device__ __forceinline__ void cpasync16(uint32_t dst_smem, const void* src) {
    asm volatile("cp.async.cg.shared.global [%0], [%1], 16;\n"
                 :: "r"(dst_smem), "l"(src));
}
__device__ __forceinline__ void ldsm4(uint32_t* r, uint32_t addr) {
    asm volatile("ldmatrix.sync.aligned.m8n8.x4.shared.b16 {%0,%1,%2,%3}, [%4];"
                 : "=r"(r[0]), "=r"(r[1]), "=r"(r[2]), "=r"(r[3]) : "r"(addr));
}
__device__ __forceinline__ void mma16816(float* d, const uint32_t* a,
                                         uint32_t b0, uint32_t b1) {
    asm volatile(
        "mma.sync.aligned.m16n8k16.row.col.f32.bf16.bf16.f32 "
        "{%0,%1,%2,%3}, {%4,%5,%6,%7}, {%8,%9}, {%0,%1,%2,%3};"
        : "+f"(d[0]), "+f"(d[1]), "+f"(d[2]), "+f"(d[3])
        : "r"(a[0]), "r"(a[1]), "r"(a[2]), "r"(a[3]), "r"(b0), "r"(b1));
}

// ---------------------------------------------------------------------------
__global__ void init_kernel() {
    int i = blockIdx.x * blockDim.x + threadIdx.x;
    if (i < 2 * B_ * H_) ((__nv_bfloat16*)g_hbf[0])[i] = __float2bfloat16(0.f);
    if (i == 0) { g_arrive = 0u; g_release = 0u; }
}

// ---------------------------------------------------------------------------
// Split x into bf16 hi/lo, pre-swizzled (key = (row>>9)&7, i.e. b&7).
// Thread per (row m, 8k-unit u): m = b*T+t, rows 512B.
// ---------------------------------------------------------------------------
__global__ __launch_bounds__(256) void split_x_kernel(const float* __restrict__ x) {
    int idx = blockIdx.x * 256 + threadIdx.x;        // 2,097,152
    int m = idx >> 5;
    int u = idx & 31;
    float v[8];
    *(float4*)&v[0] = *(const float4*)&x[(size_t)m * F_ + u * 8];
    *(float4*)&v[4] = *(const float4*)&x[(size_t)m * F_ + u * 8 + 4];
    __nv_bfloat16 hi[8], lo[8];
#pragma unroll
    for (int i = 0; i < 8; i++) {
        hi[i] = __float2bfloat16(v[i]);
        lo[i] = __float2bfloat16(v[i] - __bfloat162float(hi[i]));
    }
    int key = (m >> 9) & 7;
    size_t dst = (size_t)m * 512 + ((u ^ key) << 4);
    *(uint4*)(g_xs[0] + dst) = *(uint4*)hi;
    *(uint4*)(g_xs[1] + dst) = *(uint4*)lo;
}

// ---------------------------------------------------------------------------
// Fused W^T split: wt[n = h*4+g][k] = Wg[k][h], bf16 hi/lo pre-swizzled (key n&7).
// ---------------------------------------------------------------------------
__global__ __launch_bounds__(256) void split_w_kernel(
    const float* __restrict__ W0, const float* __restrict__ b0v,
    const float* __restrict__ W1, const float* __restrict__ b1v,
    const float* __restrict__ W2, const float* __restrict__ b2v,
    const float* __restrict__ W3, const float* __restrict__ b3v)
{
    int idx = blockIdx.x * 256 + threadIdx.x;        // 65536
    int n = idx >> 5;
    int u = idx & 31;
    int h = n >> 2, g = n & 3;
    const float* W = (g == 0) ? W0 : (g == 1) ? W1 : (g == 2) ? W2 : W3;
    __nv_bfloat16 hi[8], lo[8];
#pragma unroll
    for (int i = 0; i < 8; i++) {
        float v = W[(size_t)(u * 8 + i) * H_ + h];
        hi[i] = __float2bfloat16(v);
        lo[i] = __float2bfloat16(v - __bfloat162float(hi[i]));
    }
    size_t dst = (size_t)n * 512 + ((u ^ (n & 7)) << 4);
    *(uint4*)(g_wt[0] + dst) = *(uint4*)hi;
    *(uint4*)(g_wt[1] + dst) = *(uint4*)lo;
    if (u == 0) {
        const float* bias = (g == 0) ? b0v : (g == 1) ? b1v : (g == 2) ? b2v : b3v;
        g_bc[n] = bias[h];
    }
}

// ---------------------------------------------------------------------------
// Proj GEMM (tensor): C[t*128+b][n] = sum_k x[b*T+t][k] * wt[n][k] + bc[n]
// Block: t = blockIdx.y, n0 = blockIdx.x*64. Tile M=128(b) x N=64 x K=256.
// 3-term bf16 split. Warp w owns m-rows [w*16,w*16+16), all 4 n16-tiles.
// ---------------------------------------------------------------------------
#define PJ_A   0          // [2 buf][2 hl][128 rows][128 B] = 65536
#define PJ_B   65536      // [2 buf][2 hl][64 rows][128 B]  = 32768
#define PJ_TOT 98304

__global__ __launch_bounds__(256) void proj_mma_kernel() {
    extern __shared__ __align__(1024) char smem[];
    const uint32_t sb = smem_u32(smem);

    const int t    = blockIdx.y;
    const int n0   = blockIdx.x * 64;
    const int tid  = threadIdx.x;
    const int w    = tid >> 5;
    const int lane = tid & 31;
    const int lrow = lane & 15;
    const int lku  = lane >> 4;

    // bias regs (col mapping of D fragments)
    float2 bias_r[4][2];
#pragma unroll
    for (int nt = 0; nt < 4; nt++)
#pragma unroll
        for (int hf = 0; hf < 2; hf++) {
            int col = n0 + nt * 16 + hf * 8 + (lane & 3) * 2;
            bias_r[nt][hf] = *(const float2*)&g_bc[col];
        }

    // chunk loader lambdas (c = k-chunk 0..3)
    auto load_chunk = [&](int c, int buf) {
        // A: 128 rows x 128B x2 = 2048 x16B
#pragma unroll
        for (int i = 0; i < 8; i++) {
            int lin = i * 256 + tid;
            int hl = lin >> 10;
            int r  = lin & 1023;
            int b  = r >> 3;
            int uu = r & 7;
            const void* src = g_xs[hl] + ((size_t)(b * T_ + t) * 512 + c * 128 + uu * 16);
            cpasync16(sb + PJ_A + buf * 32768 + hl * 16384 + b * 128 + uu * 16, src);
        }
        // B: 64 rows x 128B x2 = 1024 x16B
#pragma unroll
        for (int i = 0; i < 4; i++) {
            int lin = i * 256 + tid;
            int hl = lin >> 9;
            int r  = lin & 511;
            int nl = r >> 3;
            int uu = r & 7;
            const void* src = g_wt[hl] + ((size_t)(n0 + nl) * 512 + c * 128 + uu * 16);
            cpasync16(sb + PJ_B + buf * 16384 + hl * 8192 + nl * 128 + uu * 16, src);
        }
        asm volatile("cp.async.commit_group;\n");
    };

    load_chunk(0, 0);

    float acc[4][2][4] = {};

    for (int c = 0; c < 4; c++) {
        const int buf = c & 1;
        asm volatile("cp.async.wait_group 0;\n" ::: "memory");
        __syncthreads();
        if (c + 1 < 4) load_chunk(c + 1, buf ^ 1);

        const uint32_t a_base = sb + PJ_A + buf * 32768 + (w * 16 + lrow) * 128;
        const uint32_t b_base = sb + PJ_B + buf * 16384;
        const uint32_t asw = (uint32_t)(lrow & 7);

#pragma unroll
        for (int j = 0; j < 4; j++) {
            uint32_t au = (uint32_t)(j * 2 + lku);
            uint32_t ah[4], al[4];
            ldsm4(ah, a_base + ((au ^ asw) << 4));
            ldsm4(al, a_base + 16384 + ((au ^ asw) << 4));

#pragma unroll
            for (int nt = 0; nt < 4; nt++) {
                uint32_t brow = b_base + (nt * 16 + lrow) * 128;
                uint32_t bh[4], bl[4];
                ldsm4(bh, brow + ((au ^ asw) << 4));
                ldsm4(bl, brow + 8192 + ((au ^ asw) << 4));

                mma16816(acc[nt][0], ah, bh[0], bh[2]);
                mma16816(acc[nt][0], ah, bl[0], bl[2]);
                mma16816(acc[nt][0], al, bh[0], bh[2]);
                mma16816(acc[nt][1], ah, bh[1], bh[3]);
                mma16816(acc[nt][1], ah, bl[1], bl[3]);
                mma16816(acc[nt][1], al, bh[1], bh[3]);
            }
        }
        __syncthreads();
    }

    // direct fragment store: full 32B sectors per row
    const int r0 = w * 16 + (lane >> 2);
#pragma unroll
    for (int nt = 0; nt < 4; nt++)
#pragma unroll
        for (int hf = 0; hf < 2; hf++) {
            int col = n0 + nt * 16 + hf * 8 + (lane & 3) * 2;
            float2 bb = bias_r[nt][hf];
            *(float2*)&g_xproj[((size_t)t * B_ + r0) * NG + col] =
                make_float2(acc[nt][hf][0] + bb.x, acc[nt][hf][1] + bb.y);
            *(float2*)&g_xproj[((size_t)t * B_ + r0 + 8) * NG + col] =
                make_float2(acc[nt][hf][2] + bb.x, acc[nt][hf][3] + bb.y);
        }
}

// ---------------------------------------------------------------------------
// Persistent recurrent kernel (unchanged core from R8; new xs layout only).
// ---------------------------------------------------------------------------
#define SMB_A    0
#define SMB_B    65536
#define SMB_XS   98304        // [128 b][80 B] = 10240
#define SMB_PRE  108544       // float[16][132] = 8448
#define SMB_TOT  116992

__global__ __launch_bounds__(NTHR) void recurrent_kernel(
    const float* __restrict__ Rf, const float* __restrict__ Ri,
    const float* __restrict__ Ro, const float* __restrict__ Rz)
{
    extern __shared__ __align__(1024) char smem[];
    const uint32_t sb = smem_u32(smem);

    const int bid  = blockIdx.x;
    const int tid  = threadIdx.x;
    const int w    = tid >> 5;
    const int lane = tid & 31;
    const int n0   = bid * 4;

    float* xsf = (float*)(smem + SMB_XS);
    float* pre = (float*)(smem + SMB_PRE);

    // stage split R^T into smem (once): row n = g*4+c
    {
        const float* Rm[4] = {Rf, Ri, Ro, Rz};
        for (int idx = tid; idx < 16 * H_; idx += NTHR) {
            int n = idx & 15;
            int k = idx >> 4;
            int gg = n >> 2, c = n & 3;
            float v = Rm[gg][(size_t)k * H_ + n0 + c];
            __nv_bfloat16 vhi = __float2bfloat16(v);
            __nv_bfloat16 vlo = __float2bfloat16(v - __bfloat162float(vhi));
            uint32_t u = k >> 3;
            uint32_t off = n * 1024 + ((u ^ (n & 7)) << 4) + (k & 7) * 2;
            *(__nv_bfloat16*)(smem + SMB_B + off) = vhi;
            *(__nv_bfloat16*)(smem + SMB_B + 16384 + off) = vlo;
        }
    }

    // prefetch xproj[0]: slice (t=0, all b, cols bid*16..+16), 80B padded rows
    {
#pragma unroll
        for (int e = 0; e < 2; e++) {
            int idx = e * NTHR + tid;
            int b = idx >> 2, q = idx & 3;
            const void* src = g_xproj + (size_t)b * NG + bid * 16 + q * 4;
            cpasync16(sb + SMB_XS + b * 80 + q * 16, src);
        }
        asm volatile("cp.async.commit_group;\n");
    }
    __syncthreads();

    const int lrow = lane & 15;
    const int lku  = lane >> 4;
    const uint32_t a_base = sb + SMB_A + (w * 16 + lrow) * 128;
    const uint32_t a_sw   = (w * 16 + lrow) & 7;
    const uint32_t b_base = sb + SMB_B + lrow * 1024;
    const uint32_t b_sw   = lrow & 7;

    const int ub  = tid & 127;
    const int ucp = tid >> 7;
    float c_reg[2] = {0.f, 0.f};
    float n_reg[2] = {0.f, 0.f};

    unsigned epoch = 0;

    for (int t = 0; t < T_; t++) {
        const int par = t & 1;
        const __nv_bfloat16* __restrict__ hsrc = &g_hbf[par][0][0][0];

        {
#pragma unroll
            for (int i = 0; i < 8; i++) {
                int lin = i * NTHR + tid;
                int hl = lin >> 10;
                int r  = lin & 1023;
                int m  = r >> 3;
                int s  = r & 7;
                const __nv_bfloat16* src = hsrc + ((size_t)hl * B_ + m) * H_ + s * 8;
                cpasync16(sb + SMB_A + hl * 16384 + m * 128 + ((s ^ (m & 7)) << 4), src);
            }
            asm volatile("cp.async.commit_group;\n");
        }

        float acc[2][4] = {};

        for (int kt = 0; kt < NCHUNK; kt++) {
            const int buf = kt & 1;

            if (kt + 1 < NCHUNK) {
                asm volatile("cp.async.wait_group 0;\n" ::: "memory");
                __syncthreads();
                const int nbuf = buf ^ 1;
#pragma unroll
                for (int i = 0; i < 8; i++) {
                    int lin = i * NTHR + tid;
                    int hl = lin >> 10;
                    int r  = lin & 1023;
                    int m  = r >> 3;
                    int s  = r & 7;
                    const __nv_bfloat16* src =
                        hsrc + ((size_t)hl * B_ + m) * H_ + (kt + 1) * KC + s * 8;
                    cpasync16(sb + SMB_A + nbuf * 32768 + hl * 16384 +
                              m * 128 + ((s ^ (m & 7)) << 4), src);
                }
                asm volatile("cp.async.commit_group;\n");
            } else {
                asm volatile("cp.async.wait_group 0;\n" ::: "memory");
                __syncthreads();
            }

            const uint32_t abuf = a_base + buf * 32768;
#pragma unroll
            for (int j = 0; j < 4; j++) {
                uint32_t au = (uint32_t)(j * 2 + lku);
                uint32_t bu = (uint32_t)(kt * 8 + j * 2 + lku);
                uint32_t a_hi = abuf + ((au ^ a_sw) << 4);
                uint32_t a_lo = a_hi + 16384;
                uint32_t b_hi = b_base + ((bu ^ b_sw) << 4);
                uint32_t b_lo = b_hi + 16384;

                uint32_t ah[4], al[4], bh[4], bl[4];
                ldsm4(ah, a_hi);
                ldsm4(al, a_lo);
                ldsm4(bh, b_hi);
                ldsm4(bl, b_lo);

                mma16816(acc[0], ah, bh[0], bh[2]);
                mma16816(acc[0], ah, bl[0], bl[2]);
                mma16816(acc[0], al, bh[0], bh[2]);
                mma16816(acc[1], ah, bh[1], bh[3]);
                mma16816(acc[1], ah, bl[1], bl[3]);
                mma16816(acc[1], al, bh[1], bh[3]);
            }
        }

        {
            int row0 = w * 16 + (lane >> 2);
#pragma unroll
            for (int nt = 0; nt < 2; nt++) {
                int col0 = nt * 8 + (lane & 3) * 2;
                pre[(col0    ) * 132 + row0    ] = acc[nt][0];
                pre[(col0 + 1) * 132 + row0    ] = acc[nt][1];
                pre[(col0    ) * 132 + row0 + 8] = acc[nt][2];
                pre[(col0 + 1) * 132 + row0 + 8] = acc[nt][3];
            }
        }
        __syncthreads();

        // pointwise sLSTM update; xs layout: xsf[b*20 + c*4 + g]
        {
            const int np = par ^ 1;
            uint32_t phi, plo;
            __nv_bfloat16* vhi = (__nv_bfloat16*)&phi;
            __nv_bfloat16* vlo = (__nv_bfloat16*)&plo;
#pragma unroll
            for (int e = 0; e < 2; e++) {
                int c = ucp * 2 + e;
                float ft = pre[(0 * 4 + c) * 132 + ub] + xsf[ub * 20 + c * 4 + 0];
                float it = pre[(1 * 4 + c) * 132 + ub] + xsf[ub * 20 + c * 4 + 1];
                float ot = pre[(2 * 4 + c) * 132 + ub] + xsf[ub * 20 + c * 4 + 2];
                float zt = pre[(3 * 4 + c) * 132 + ub] + xsf[ub * 20 + c * 4 + 3];

                float o  = __fdividef(1.f, 1.f + __expf(-ot));
                float z  = 1.f - __fdividef(2.f, __expf(2.f * zt) + 1.f);
                float fh = __expf(fminf(ft, 10.f));
                float ih = __expf(fminf(it, 10.f));
                float rd = __fdividef(1.f, fh + ih + 1e-8f);
                float f  = fh * rd;
                float ii = ih * rd;
                c_reg[e] = f * c_reg[e] + ii * z;
                n_reg[e] = f * n_reg[e] + ii;
                float hv = o * __fdividef(c_reg[e], n_reg[e] + 1e-8f);

                vhi[e] = __float2bfloat16(hv);
                vlo[e] = __float2bfloat16(hv - __bfloat162float(vhi[e]));
            }
            *(uint32_t*)&g_hbf[np][0][ub][n0 + ucp * 2] = phi;
            *(uint32_t*)&g_hbf[np][1][ub][n0 + ucp * 2] = plo;
        }

        __syncthreads();

        // prefetch xproj[t+1] in barrier shadow
        {
            int tn = (t + 1 < T_) ? (t + 1) : t;
#pragma unroll
            for (int e = 0; e < 2; e++) {
                int idx = e * NTHR + tid;
                int b = idx >> 2, q = idx & 3;
                const void* src = g_xproj + ((size_t)tn * B_ + b) * NG + bid * 16 + q * 4;
                cpasync16(sb + SMB_XS + b * 80 + q * 16, src);
            }
            asm volatile("cp.async.commit_group;\n");
        }

        epoch++;
        if (tid == 0) {
            __threadfence();
            unsigned a = atomicAdd((unsigned*)&g_arrive, 1u) + 1u;
            if (a == epoch * NBLK) {
                g_release = epoch;
                __threadfence();
            } else {
                while (g_release < epoch) { }
                __threadfence();
            }
        }
        __syncthreads();
    }

    asm volatile("cp.async.wait_group 0;\n" ::: "memory");
}

// ---------------------------------------------------------------------------
__global__ __launch_bounds__(128) void head_kernel(
    const float* __restrict__ fcw, const float* __restrict__ fcb,
    float* __restrict__ out)
{
    int b = blockIdx.x;
    float s = 0.f;
    for (int k = threadIdx.x; k < H_; k += 128) {
        float hv = __bfloat162float(g_hbf[0][0][b][k]) +
                   __bfloat162float(g_hbf[0][1][b][k]);
        s += hv * fcw[k];
    }

    __shared__ float red[4];
#pragma unroll
    for (int off = 16; off; off >>= 1)
        s += __shfl_down_sync(0xffffffff, s, off);
    if ((threadIdx.x & 31) == 0) red[threadIdx.x >> 5] = s;
    __syncthreads();
    if (threadIdx.x == 0) {
        float tot = red[0] + red[1] + red[2] + red[3];
        out[b] = tanhf(tot + fcb[0]);
    }
}

// ---------------------------------------------------------------------------
extern "C" void kernel_launch(void* const* d_in, const int* in_sizes, int n_in,
                              void* d_out, int out_size)
{
    const float* x   = (const float*)d_in[0];
    const float* Wf  = (const float*)d_in[1];
    const float* bf  = (const float*)d_in[2];
    const float* Wi  = (const float*)d_in[3];
    const float* bi  = (const float*)d_in[4];
    const float* Wo  = (const float*)d_in[5];
    const float* bo  = (const float*)d_in[6];
    const float* Wz  = (const float*)d_in[7];
    const float* bz  = (const float*)d_in[8];
    const float* Rf  = (const float*)d_in[9];
    const float* Ri  = (const float*)d_in[10];
    const float* Ro  = (const float*)d_in[11];
    const float* Rz  = (const float*)d_in[12];
    const float* fcw = (const float*)d_in[13];
    const float* fcb = (const float*)d_in[14];
    float* out = (float*)d_out;

    cudaFuncSetAttribute(recurrent_kernel,
                         cudaFuncAttributeMaxDynamicSharedMemorySize, SMB_TOT);
    cudaFuncSetAttribute(proj_mma_kernel,
                         cudaFuncAttributeMaxDynamicSharedMemorySize, PJ_TOT);

    init_kernel<<<(2 * B_ * H_ + 255) / 256, 256>>>();

    split_x_kernel<<<(B_ * T_ * 32) / 256, 256>>>(x);
    split_w_kernel<<<(NG * 32) / 256, 256>>>(Wf, bf, Wi, bi, Wo, bo, Wz, bz);

    dim3 gP(NG / 64, T_);
    proj_mma_kernel<<<gP, 256, PJ_TOT>>>();

    recurrent_kernel<<<NBLK, NTHR, SMB_TOT>>>(Rf, Ri, Ro, Rz);

    head_kernel<<<B_, 128>>>(fcw, fcb, out);
}

// round 10
// speedup vs baseline: 3.8391x; 1.1704x over previous
#include <cuda_runtime.h>
#include <cuda_bf16.h>
#include <math.h>
#include <stdint.h>

#define B_ 128
#define T_ 512
#define F_ 256
#define H_ 512
#define NG 2048               // H_*4 fused gate cols, n = h*4+g
#define NBLK 128
#define NTHR 256
#define KC 64
#define NCHUNK (H_ / KC)      // 8

// ---------------- device globals (allocation-free scratch) ------------------
__device__ float g_xproj[(size_t)T_ * B_ * NG];             // [t][b][n]
__device__ unsigned char g_xs[2][(size_t)B_ * T_ * F_ * 2]; // bf16 hi/lo, pre-swizzled
__device__ unsigned char g_wt[2][(size_t)NG * F_ * 2];      // bf16 hi/lo W^T, pre-swizzled
__device__ float g_bc[NG];                                  // fused bias
__device__ __nv_bfloat16 g_hbf[2][2][B_][H_];               // [parity][hi/lo][b][k]
__device__ volatile unsigned g_arrive;
__device__ volatile unsigned g_release;

// ---------------------------------------------------------------------------
__device__ __forceinline__ uint32_t smem_u32(const void* p) {
    uint32_t a;
    asm("{ .reg .u64 t; cvta.to.shared.u64 t, %1; cvt.u32.u64 %0, t; }" : "=r"(a) : "l"(p));
    return a;
}
__device__ __forceinline__ void cpasync16(uint32_t dst_smem, const void* src) {
    asm volatile("cp.async.cg.shared.global [%0], [%1], 16;\n"
                 :: "r"(dst_smem), "l"(src));
}
__device__ __forceinline__ void ldsm4(uint32_t* r, uint32_t addr) {
    asm volatile("ldmatrix.sync.aligned.m8n8.x4.shared.b16 {%0,%1,%2,%3}, [%4];"
                 : "=r"(r[0]), "=r"(r[1]), "=r"(r[2]), "=r"(r[3]) : "r"(addr));
}
__device__ __forceinline__ void mma16816(float* d, const uint32_t* a,
                                         uint32_t b0, uint32_t b1) {
    asm volatile(
        "mma.sync.aligned.m16n8k16.row.col.f32.bf16.bf16.f32 "
        "{%0,%1,%2,%3}, {%4,%5,%6,%7}, {%8,%9}, {%0,%1,%2,%3};"
        : "+f"(d[0]), "+f"(d[1]), "+f"(d[2]), "+f"(d[3])
        : "r"(a[0]), "r"(a[1]), "r"(a[2]), "r"(a[3]), "r"(b0), "r"(b1));
}

// ---------------------------------------------------------------------------
__global__ void init_kernel() {
    int i = blockIdx.x * blockDim.x + threadIdx.x;
    if (i < 2 * B_ * H_) ((__nv_bfloat16*)g_hbf[0])[i] = __float2bfloat16(0.f);
    if (i == 0) { g_arrive = 0u; g_release = 0u; }
}

// ---------------------------------------------------------------------------
__global__ __launch_bounds__(256) void split_x_kernel(const float* __restrict__ x) {
    int idx = blockIdx.x * 256 + threadIdx.x;
    int m = idx >> 5;
    int u = idx & 31;
    float v[8];
    *(float4*)&v[0] = *(const float4*)&x[(size_t)m * F_ + u * 8];
    *(float4*)&v[4] = *(const float4*)&x[(size_t)m * F_ + u * 8 + 4];
    __nv_bfloat16 hi[8], lo[8];
#pragma unroll
    for (int i = 0; i < 8; i++) {
        hi[i] = __float2bfloat16(v[i]);
        lo[i] = __float2bfloat16(v[i] - __bfloat162float(hi[i]));
    }
    int key = (m >> 9) & 7;
    size_t dst = (size_t)m * 512 + ((u ^ key) << 4);
    *(uint4*)(g_xs[0] + dst) = *(uint4*)hi;
    *(uint4*)(g_xs[1] + dst) = *(uint4*)lo;
}

// ---------------------------------------------------------------------------
__global__ __launch_bounds__(256) void split_w_kernel(
    const float* __restrict__ W0, const float* __restrict__ b0v,
    const float* __restrict__ W1, const float* __restrict__ b1v,
    const float* __restrict__ W2, const float* __restrict__ b2v,
    const float* __restrict__ W3, const float* __restrict__ b3v)
{
    int idx = blockIdx.x * 256 + threadIdx.x;
    int n = idx >> 5;
    int u = idx & 31;
    int h = n >> 2, g = n & 3;
    const float* W = (g == 0) ? W0 : (g == 1) ? W1 : (g == 2) ? W2 : W3;
    __nv_bfloat16 hi[8], lo[8];
#pragma unroll
    for (int i = 0; i < 8; i++) {
        float v = W[(size_t)(u * 8 + i) * H_ + h];
        hi[i] = __float2bfloat16(v);
        lo[i] = __float2bfloat16(v - __bfloat162float(hi[i]));
    }
    size_t dst = (size_t)n * 512 + ((u ^ (n & 7)) << 4);
    *(uint4*)(g_wt[0] + dst) = *(uint4*)hi;
    *(uint4*)(g_wt[1] + dst) = *(uint4*)lo;
    if (u == 0) {
        const float* bias = (g == 0) ? b0v : (g == 1) ? b1v : (g == 2) ? b2v : b3v;
        g_bc[n] = bias[h];
    }
}

// ---------------------------------------------------------------------------
// Proj GEMM (tensor) — unchanged from R9.
// ---------------------------------------------------------------------------
#define PJ_A   0
#define PJ_B   65536
#define PJ_TOT 98304

__global__ __launch_bounds__(256) void proj_mma_kernel() {
    extern __shared__ __align__(1024) char smem[];
    const uint32_t sb = smem_u32(smem);

    const int t    = blockIdx.y;
    const int n0   = blockIdx.x * 64;
    const int tid  = threadIdx.x;
    const int w    = tid >> 5;
    const int lane = tid & 31;
    const int lrow = lane & 15;
    const int lku  = lane >> 4;

    float2 bias_r[4][2];
#pragma unroll
    for (int nt = 0; nt < 4; nt++)
#pragma unroll
        for (int hf = 0; hf < 2; hf++) {
            int col = n0 + nt * 16 + hf * 8 + (lane & 3) * 2;
            bias_r[nt][hf] = *(const float2*)&g_bc[col];
        }

    auto load_chunk = [&](int c, int buf) {
#pragma unroll
        for (int i = 0; i < 8; i++) {
            int lin = i * 256 + tid;
            int hl = lin >> 10;
            int r  = lin & 1023;
            int b  = r >> 3;
            int uu = r & 7;
            const void* src = g_xs[hl] + ((size_t)(b * T_ + t) * 512 + c * 128 + uu * 16);
            cpasync16(sb + PJ_A + buf * 32768 + hl * 16384 + b * 128 + uu * 16, src);
        }
#pragma unroll
        for (int i = 0; i < 4; i++) {
            int lin = i * 256 + tid;
            int hl = lin >> 9;
            int r  = lin & 511;
            int nl = r >> 3;
            int uu = r & 7;
            const void* src = g_wt[hl] + ((size_t)(n0 + nl) * 512 + c * 128 + uu * 16);
            cpasync16(sb + PJ_B + buf * 16384 + hl * 8192 + nl * 128 + uu * 16, src);
        }
        asm volatile("cp.async.commit_group;\n");
    };

    load_chunk(0, 0);

    float acc[4][2][4] = {};

    for (int c = 0; c < 4; c++) {
        const int buf = c & 1;
        asm volatile("cp.async.wait_group 0;\n" ::: "memory");
        __syncthreads();
        if (c + 1 < 4) load_chunk(c + 1, buf ^ 1);

        const uint32_t a_base = sb + PJ_A + buf * 32768 + (w * 16 + lrow) * 128;
        const uint32_t b_base = sb + PJ_B + buf * 16384;
        const uint32_t asw = (uint32_t)(lrow & 7);

#pragma unroll
        for (int j = 0; j < 4; j++) {
            uint32_t au = (uint32_t)(j * 2 + lku);
            uint32_t ah[4], al[4];
            ldsm4(ah, a_base + ((au ^ asw) << 4));
            ldsm4(al, a_base + 16384 + ((au ^ asw) << 4));

#pragma unroll
            for (int nt = 0; nt < 4; nt++) {
                uint32_t brow = b_base + (nt * 16 + lrow) * 128;
                uint32_t bh[4], bl[4];
                ldsm4(bh, brow + ((au ^ asw) << 4));
                ldsm4(bl, brow + 8192 + ((au ^ asw) << 4));

                mma16816(acc[nt][0], ah, bh[0], bh[2]);
                mma16816(acc[nt][0], ah, bl[0], bl[2]);
                mma16816(acc[nt][0], al, bh[0], bh[2]);
                mma16816(acc[nt][1], ah, bh[1], bh[3]);
                mma16816(acc[nt][1], ah, bl[1], bl[3]);
                mma16816(acc[nt][1], al, bh[1], bh[3]);
            }
        }
        __syncthreads();
    }

    const int r0 = w * 16 + (lane >> 2);
#pragma unroll
    for (int nt = 0; nt < 4; nt++)
#pragma unroll
        for (int hf = 0; hf < 2; hf++) {
            int col = n0 + nt * 16 + hf * 8 + (lane & 3) * 2;
            float2 bb = bias_r[nt][hf];
            *(float2*)&g_xproj[((size_t)t * B_ + r0) * NG + col] =
                make_float2(acc[nt][hf][0] + bb.x, acc[nt][hf][1] + bb.y);
            *(float2*)&g_xproj[((size_t)t * B_ + r0 + 8) * NG + col] =
                make_float2(acc[nt][hf][2] + bb.x, acc[nt][hf][3] + bb.y);
        }
}

// ---------------------------------------------------------------------------
// Persistent recurrent kernel, repartitioned:
//   block bid: cg = bid>>2 (32 col-groups: h-cols cg*16..+16, gate cols cg*64..+64),
//              bg = bid&3  (4 batch-groups: batches bg*32..+32)
// Per step: D[32 m x 64 n] = h_rows(bg) @ R_slice(cg), 3-term bf16 split.
// L2 traffic: 64KB/block/step (vs 256KB before).
// ---------------------------------------------------------------------------
#define SMB_A    0            // [2 buf][2 hl][32 rows][128 B] = 16384
#define SMB_B    16384        // [2 hl][64 n][1024 B] = 131072
#define SMB_XS   147456       // [32 b][272 B] = 8704
#define SMB_PRE  156160       // float[64 n][36 m] = 9216
#define SMB_TOT  165376

__global__ __launch_bounds__(NTHR) void recurrent_kernel(
    const float* __restrict__ Rf, const float* __restrict__ Ri,
    const float* __restrict__ Ro, const float* __restrict__ Rz)
{
    extern __shared__ __align__(1024) char smem[];
    const uint32_t sb = smem_u32(smem);

    const int bid  = blockIdx.x;
    const int tid  = threadIdx.x;
    const int w    = tid >> 5;
    const int lane = tid & 31;
    const int cg   = bid >> 2;       // col group 0..31
    const int bg   = bid & 3;        // batch group 0..3

    float* xsf = (float*)(smem + SMB_XS);
    float* pre = (float*)(smem + SMB_PRE);

    // stage split R^T slice (once): row n = h_loc*4+g (64 rows), 512 k
    {
        const float* Rm[4] = {Rf, Ri, Ro, Rz};
        for (int idx = tid; idx < 64 * H_; idx += NTHR) {
            int n = idx & 63;
            int k = idx >> 6;
            int hl = n >> 2, g = n & 3;
            float v = Rm[g][(size_t)k * H_ + cg * 16 + hl];
            __nv_bfloat16 vhi = __float2bfloat16(v);
            __nv_bfloat16 vlo = __float2bfloat16(v - __bfloat162float(vhi));
            uint32_t off = n * 1024 + ((((uint32_t)k >> 3) ^ (n & 7)) << 4) + (k & 7) * 2;
            *(__nv_bfloat16*)(smem + SMB_B + off) = vhi;
            *(__nv_bfloat16*)(smem + SMB_B + 65536 + off) = vlo;
        }
    }

    // prefetch xproj[0] slice: 32 b x 64 cols (256B/row -> 272B padded)
    {
#pragma unroll
        for (int e = 0; e < 2; e++) {
            int idx = e * NTHR + tid;
            int b = idx >> 4, u = idx & 15;
            const void* src = g_xproj + (size_t)(bg * 32 + b) * NG + cg * 64 + u * 4;
            cpasync16(sb + SMB_XS + b * 272 + u * 16, src);
        }
        asm volatile("cp.async.commit_group;\n");
    }
    __syncthreads();

    // MMA mapping: wm = w&1 (m-tile of 16), wn = w>>1 (n-tile of 16)
    const int wm = w & 1;
    const int wn = w >> 1;
    const int lrow = lane & 15;
    const int lku  = lane >> 4;
    const uint32_t a_row_off = (uint32_t)((wm * 16 + lrow) * 128);
    const uint32_t a_sw      = (uint32_t)(lrow & 7);
    const uint32_t b_base    = sb + SMB_B + (wn * 16 + lrow) * 1024;
    const uint32_t b_sw      = (uint32_t)(lrow & 7);

    // update mapping: thread -> (batch b_loc, h-col pair 2q,2q+1)
    const int ub = tid >> 3;         // 0..31
    const int uq = tid & 7;          // 0..7
    float c_reg[2] = {0.f, 0.f};
    float n_reg[2] = {0.f, 0.f};

    unsigned epoch = 0;

    for (int t = 0; t < T_; t++) {
        const int par = t & 1;
        const __nv_bfloat16* __restrict__ hsrc = &g_hbf[par][0][0][0];

        // load chunk 0 (8KB: 512 x 16B, 2 per thread)
        {
#pragma unroll
            for (int i = 0; i < 2; i++) {
                int lin = i * NTHR + tid;
                int hl = lin >> 8;
                int r  = lin & 255;
                int m  = r >> 3;
                int s  = r & 7;
                const __nv_bfloat16* src =
                    hsrc + ((size_t)hl * B_ + bg * 32 + m) * H_ + s * 8;
                cpasync16(sb + SMB_A + hl * 4096 + m * 128 + ((s ^ (m & 7)) << 4), src);
            }
            asm volatile("cp.async.commit_group;\n");
        }

        float acc[2][4] = {};

        for (int kt = 0; kt < NCHUNK; kt++) {
            const int buf = kt & 1;

            asm volatile("cp.async.wait_group 0;\n" ::: "memory");
            __syncthreads();
            if (kt + 1 < NCHUNK) {
                const int nbuf = buf ^ 1;
#pragma unroll
                for (int i = 0; i < 2; i++) {
                    int lin = i * NTHR + tid;
                    int hl = lin >> 8;
                    int r  = lin & 255;
                    int m  = r >> 3;
                    int s  = r & 7;
                    const __nv_bfloat16* src =
                        hsrc + ((size_t)hl * B_ + bg * 32 + m) * H_ + (kt + 1) * KC + s * 8;
                    cpasync16(sb + SMB_A + nbuf * 8192 + hl * 4096 +
                              m * 128 + ((s ^ (m & 7)) << 4), src);
                }
                asm volatile("cp.async.commit_group;\n");
            }

            const uint32_t abuf = sb + SMB_A + buf * 8192 + a_row_off;
#pragma unroll
            for (int j = 0; j < 4; j++) {
                uint32_t au = (uint32_t)(j * 2 + lku);
                uint32_t bu = (uint32_t)(kt * 8 + j * 2 + lku);
                uint32_t a_hi = abuf + ((au ^ a_sw) << 4);
                uint32_t a_lo = a_hi + 4096;
                uint32_t b_hi = b_base + ((bu ^ b_sw) << 4);
                uint32_t b_lo = b_hi + 65536;

                uint32_t ah[4], al[4], bh[4], bl[4];
                ldsm4(ah, a_hi);
                ldsm4(al, a_lo);
                ldsm4(bh, b_hi);
                ldsm4(bl, b_lo);

                mma16816(acc[0], ah, bh[0], bh[2]);
                mma16816(acc[0], ah, bl[0], bl[2]);
                mma16816(acc[0], al, bh[0], bh[2]);
                mma16816(acc[1], ah, bh[1], bh[3]);
                mma16816(acc[1], ah, bl[1], bl[3]);
                mma16816(acc[1], al, bh[1], bh[3]);
            }
        }

        // epilogue: D fragments -> pre[n][m] (stride 36)
        {
            int row0 = wm * 16 + (lane >> 2);
#pragma unroll
            for (int nt = 0; nt < 2; nt++) {
                int col0 = wn * 16 + nt * 8 + (lane & 3) * 2;
                pre[(col0    ) * 36 + row0    ] = acc[nt][0];
                pre[(col0 + 1) * 36 + row0    ] = acc[nt][1];
                pre[(col0    ) * 36 + row0 + 8] = acc[nt][2];
                pre[(col0 + 1) * 36 + row0 + 8] = acc[nt][3];
            }
        }
        __syncthreads();

        // pointwise sLSTM update
        {
            const int np = par ^ 1;
            const int gb = bg * 32 + ub;     // global batch
            uint32_t phi, plo;
            __nv_bfloat16* vhi = (__nv_bfloat16*)&phi;
            __nv_bfloat16* vlo = (__nv_bfloat16*)&plo;
#pragma unroll
            for (int e = 0; e < 2; e++) {
                int hc = uq * 2 + e;         // local h-col 0..15
                float ft = pre[(hc * 4 + 0) * 36 + ub] + xsf[ub * 68 + hc * 4 + 0];
                float it = pre[(hc * 4 + 1) * 36 + ub] + xsf[ub * 68 + hc * 4 + 1];
                float ot = pre[(hc * 4 + 2) * 36 + ub] + xsf[ub * 68 + hc * 4 + 2];
                float zt = pre[(hc * 4 + 3) * 36 + ub] + xsf[ub * 68 + hc * 4 + 3];

                float o  = __fdividef(1.f, 1.f + __expf(-ot));
                float z  = 1.f - __fdividef(2.f, __expf(2.f * zt) + 1.f);
                float fh = __expf(fminf(ft, 10.f));
                float ih = __expf(fminf(it, 10.f));
                float rd = __fdividef(1.f, fh + ih + 1e-8f);
                float f  = fh * rd;
                float ii = ih * rd;
                c_reg[e] = f * c_reg[e] + ii * z;
                n_reg[e] = f * n_reg[e] + ii;
                float hv = o * __fdividef(c_reg[e], n_reg[e] + 1e-8f);

                vhi[e] = __float2bfloat16(hv);
                vlo[e] = __float2bfloat16(hv - __bfloat162float(vhi[e]));
            }
            *(uint32_t*)&g_hbf[np][0][gb][cg * 16 + uq * 2] = phi;
            *(uint32_t*)&g_hbf[np][1][gb][cg * 16 + uq * 2] = plo;
        }

        __syncthreads();

        // prefetch xproj[t+1] in barrier shadow
        {
            int tn = (t + 1 < T_) ? (t + 1) : t;
#pragma unroll
            for (int e = 0; e < 2; e++) {
                int idx = e * NTHR + tid;
                int b = idx >> 4, u = idx & 15;
                const void* src = g_xproj + ((size_t)tn * B_ + bg * 32 + b) * NG
                                + cg * 64 + u * 4;
                cpasync16(sb + SMB_XS + b * 272 + u * 16, src);
            }
            asm volatile("cp.async.commit_group;\n");
        }

        // grid barrier
        epoch++;
        if (tid == 0) {
            __threadfence();
            unsigned a = atomicAdd((unsigned*)&g_arrive, 1u) + 1u;
            if (a == epoch * NBLK) {
                g_release = epoch;
                __threadfence();
            } else {
                while (g_release < epoch) { }
                __threadfence();
            }
        }
        __syncthreads();
    }

    asm volatile("cp.async.wait_group 0;\n" ::: "memory");
}

// ---------------------------------------------------------------------------
__global__ __launch_bounds__(128) void head_kernel(
    const float* __restrict__ fcw, const float* __restrict__ fcb,
    float* __restrict__ out)
{
    int b = blockIdx.x;
    float s = 0.f;
    for (int k = threadIdx.x; k < H_; k += 128) {
        float hv = __bfloat162float(g_hbf[0][0][b][k]) +
                   __bfloat162float(g_hbf[0][1][b][k]);
        s += hv * fcw[k];
    }

    __shared__ float red[4];
#pragma unroll
    for (int off = 16; off; off >>= 1)
        s += __shfl_down_sync(0xffffffff, s, off);
    if ((threadIdx.x & 31) == 0) red[threadIdx.x >> 5] = s;
    __syncthreads();
    if (threadIdx.x == 0) {
        float tot = red[0] + red[1] + red[2] + red[3];
        out[b] = tanhf(tot + fcb[0]);
    }
}

// ---------------------------------------------------------------------------
extern "C" void kernel_launch(void* const* d_in, const int* in_sizes, int n_in,
                              void* d_out, int out_size)
{
    const float* x   = (const float*)d_in[0];
    const float* Wf  = (const float*)d_in[1];
    const float* bf  = (const float*)d_in[2];
    const float* Wi  = (const float*)d_in[3];
    const float* bi  = (const float*)d_in[4];
    const float* Wo  = (const float*)d_in[5];
    const float* bo  = (const float*)d_in[6];
    const float* Wz  = (const float*)d_in[7];
    const float* bz  = (const float*)d_in[8];
    const float* Rf  = (const float*)d_in[9];
    const float* Ri  = (const float*)d_in[10];
    const float* Ro  = (const float*)d_in[11];
    const float* Rz  = (const float*)d_in[12];
    const float* fcw = (const float*)d_in[13];
    const float* fcb = (const float*)d_in[14];
    float* out = (float*)d_out;

    cudaFuncSetAttribute(recurrent_kernel,
                         cudaFuncAttributeMaxDynamicSharedMemorySize, SMB_TOT);
    cudaFuncSetAttribute(proj_mma_kernel,
                         cudaFuncAttributeMaxDynamicSharedMemorySize, PJ_TOT);

    init_kernel<<<(2 * B_ * H_ + 255) / 256, 256>>>();

    split_x_kernel<<<(B_ * T_ * 32) / 256, 256>>>(x);
    split_w_kernel<<<(NG * 32) / 256, 256>>>(Wf, bf, Wi, bi, Wo, bo, Wz, bz);

    dim3 gP(NG / 64, T_);
    proj_mma_kernel<<<gP, 256, PJ_TOT>>>();

    recurrent_kernel<<<NBLK, NTHR, SMB_TOT>>>(Rf, Ri, Ro, Rz);

    head_kernel<<<B_, 128>>>(fcw, fcb, out);
}

// round 11
// speedup vs baseline: 3.8707x; 1.0082x over previous
#include <cuda_runtime.h>
#include <cuda_bf16.h>
#include <math.h>
#include <stdint.h>

#define B_ 128
#define T_ 512
#define F_ 256
#define H_ 512
#define NG 2048               // H_*4 fused gate cols, n = h*4+g
#define NBLK 128
#define NTHR 256

// ---------------- device globals (allocation-free scratch) ------------------
__device__ float g_xproj[(size_t)T_ * B_ * NG];             // [t][b][n]
__device__ unsigned char g_xs[2][(size_t)B_ * T_ * F_ * 2]; // bf16 hi/lo, pre-swizzled
__device__ unsigned char g_wt[2][(size_t)NG * F_ * 2];      // bf16 hi/lo W^T, pre-swizzled
__device__ float g_bc[NG];                                  // fused bias
__device__ __nv_bfloat16 g_hbf[2][2][B_][H_];               // [parity][hi/lo][b][k]
__device__ volatile unsigned g_arrive4[4 * 32];             // 128B-spaced per-group
__device__ volatile unsigned g_release4[4 * 32];

// ---------------------------------------------------------------------------
__device__ __forceinline__ uint32_t smem_u32(const void* p) {
    uint32_t a;
    asm("{ .reg .u64 t; cvta.to.shared.u64 t, %1; cvt.u32.u64 %0, t; }" : "=r"(a) : "l"(p));
    return a;
}
__device__ __forceinline__ void cpasync16(uint32_t dst_smem, const void* src) {
    asm volatile("cp.async.cg.shared.global [%0], [%1], 16;\n"
                 :: "r"(dst_smem), "l"(src));
}
__device__ __forceinline__ void ldsm4(uint32_t* r, uint32_t addr) {
    asm volatile("ldmatrix.sync.aligned.m8n8.x4.shared.b16 {%0,%1,%2,%3}, [%4];"
                 : "=r"(r[0]), "=r"(r[1]), "=r"(r[2]), "=r"(r[3]) : "r"(addr));
}
__device__ __forceinline__ void mma16816(float* d, const uint32_t* a,
                                         uint32_t b0, uint32_t b1) {
    asm volatile(
        "mma.sync.aligned.m16n8k16.row.col.f32.bf16.bf16.f32 "
        "{%0,%1,%2,%3}, {%4,%5,%6,%7}, {%8,%9}, {%0,%1,%2,%3};"
        : "+f"(d[0]), "+f"(d[1]), "+f"(d[2]), "+f"(d[3])
        : "r"(a[0]), "r"(a[1]), "r"(a[2]), "r"(a[3]), "r"(b0), "r"(b1));
}

// ---------------------------------------------------------------------------
__global__ void init_kernel() {
    int i = blockIdx.x * blockDim.x + threadIdx.x;
    if (i < 2 * B_ * H_) ((__nv_bfloat16*)g_hbf[0])[i] = __float2bfloat16(0.f);
    if (i < 4 * 32) { g_arrive4[i] = 0u; g_release4[i] = 0u; }
}

// ---------------------------------------------------------------------------
__global__ __launch_bounds__(256) void split_x_kernel(const float* __restrict__ x) {
    int idx = blockIdx.x * 256 + threadIdx.x;
    int m = idx >> 5;
    int u = idx & 31;
    float v[8];
    *(float4*)&v[0] = *(const float4*)&x[(size_t)m * F_ + u * 8];
    *(float4*)&v[4] = *(const float4*)&x[(size_t)m * F_ + u * 8 + 4];
    __nv_bfloat16 hi[8], lo[8];
#pragma unroll
    for (int i = 0; i < 8; i++) {
        hi[i] = __float2bfloat16(v[i]);
        lo[i] = __float2bfloat16(v[i] - __bfloat162float(hi[i]));
    }
    int key = (m >> 9) & 7;
    size_t dst = (size_t)m * 512 + ((u ^ key) << 4);
    *(uint4*)(g_xs[0] + dst) = *(uint4*)hi;
    *(uint4*)(g_xs[1] + dst) = *(uint4*)lo;
}

// ---------------------------------------------------------------------------
__global__ __launch_bounds__(256) void split_w_kernel(
    const float* __restrict__ W0, const float* __restrict__ b0v,
    const float* __restrict__ W1, const float* __restrict__ b1v,
    const float* __restrict__ W2, const float* __restrict__ b2v,
    const float* __restrict__ W3, const float* __restrict__ b3v)
{
    int idx = blockIdx.x * 256 + threadIdx.x;
    int n = idx >> 5;
    int u = idx & 31;
    int h = n >> 2, g = n & 3;
    const float* W = (g == 0) ? W0 : (g == 1) ? W1 : (g == 2) ? W2 : W3;
    __nv_bfloat16 hi[8], lo[8];
#pragma unroll
    for (int i = 0; i < 8; i++) {
        float v = W[(size_t)(u * 8 + i) * H_ + h];
        hi[i] = __float2bfloat16(v);
        lo[i] = __float2bfloat16(v - __bfloat162float(hi[i]));
    }
    size_t dst = (size_t)n * 512 + ((u ^ (n & 7)) << 4);
    *(uint4*)(g_wt[0] + dst) = *(uint4*)hi;
    *(uint4*)(g_wt[1] + dst) = *(uint4*)lo;
    if (u == 0) {
        const float* bias = (g == 0) ? b0v : (g == 1) ? b1v : (g == 2) ? b2v : b3v;
        g_bc[n] = bias[h];
    }
}

// ---------------------------------------------------------------------------
// Proj GEMM (tensor) — unchanged from R9/R10.
// ---------------------------------------------------------------------------
#define PJ_A   0
#define PJ_B   65536
#define PJ_TOT 98304

__global__ __launch_bounds__(256) void proj_mma_kernel() {
    extern __shared__ __align__(1024) char smem[];
    const uint32_t sb = smem_u32(smem);

    const int t    = blockIdx.y;
    const int n0   = blockIdx.x * 64;
    const int tid  = threadIdx.x;
    const int w    = tid >> 5;
    const int lane = tid & 31;
    const int lrow = lane & 15;
    const int lku  = lane >> 4;

    float2 bias_r[4][2];
#pragma unroll
    for (int nt = 0; nt < 4; nt++)
#pragma unroll
        for (int hf = 0; hf < 2; hf++) {
            int col = n0 + nt * 16 + hf * 8 + (lane & 3) * 2;
            bias_r[nt][hf] = *(const float2*)&g_bc[col];
        }

    auto load_chunk = [&](int c, int buf) {
#pragma unroll
        for (int i = 0; i < 8; i++) {
            int lin = i * 256 + tid;
            int hl = lin >> 10;
            int r  = lin & 1023;
            int b  = r >> 3;
            int uu = r & 7;
            const void* src = g_xs[hl] + ((size_t)(b * T_ + t) * 512 + c * 128 + uu * 16);
            cpasync16(sb + PJ_A + buf * 32768 + hl * 16384 + b * 128 + uu * 16, src);
        }
#pragma unroll
        for (int i = 0; i < 4; i++) {
            int lin = i * 256 + tid;
            int hl = lin >> 9;
            int r  = lin & 511;
            int nl = r >> 3;
            int uu = r & 7;
            const void* src = g_wt[hl] + ((size_t)(n0 + nl) * 512 + c * 128 + uu * 16);
            cpasync16(sb + PJ_B + buf * 16384 + hl * 8192 + nl * 128 + uu * 16, src);
        }
        asm volatile("cp.async.commit_group;\n");
    };

    load_chunk(0, 0);

    float acc[4][2][4] = {};

    for (int c = 0; c < 4; c++) {
        const int buf = c & 1;
        asm volatile("cp.async.wait_group 0;\n" ::: "memory");
        __syncthreads();
        if (c + 1 < 4) load_chunk(c + 1, buf ^ 1);

        const uint32_t a_base = sb + PJ_A + buf * 32768 + (w * 16 + lrow) * 128;
        const uint32_t b_base = sb + PJ_B + buf * 16384;
        const uint32_t asw = (uint32_t)(lrow & 7);

#pragma unroll
        for (int j = 0; j < 4; j++) {
            uint32_t au = (uint32_t)(j * 2 + lku);
            uint32_t ah[4], al[4];
            ldsm4(ah, a_base + ((au ^ asw) << 4));
            ldsm4(al, a_base + 16384 + ((au ^ asw) << 4));

#pragma unroll
            for (int nt = 0; nt < 4; nt++) {
                uint32_t brow = b_base + (nt * 16 + lrow) * 128;
                uint32_t bh[4], bl[4];
                ldsm4(bh, brow + ((au ^ asw) << 4));
                ldsm4(bl, brow + 8192 + ((au ^ asw) << 4));

                mma16816(acc[nt][0], ah, bh[0], bh[2]);
                mma16816(acc[nt][0], ah, bl[0], bl[2]);
                mma16816(acc[nt][0], al, bh[0], bh[2]);
                mma16816(acc[nt][1], ah, bh[1], bh[3]);
                mma16816(acc[nt][1], ah, bl[1], bl[3]);
                mma16816(acc[nt][1], al, bh[1], bh[3]);
            }
        }
        __syncthreads();
    }

    const int r0 = w * 16 + (lane >> 2);
#pragma unroll
    for (int nt = 0; nt < 4; nt++)
#pragma unroll
        for (int hf = 0; hf < 2; hf++) {
            int col = n0 + nt * 16 + hf * 8 + (lane & 3) * 2;
            float2 bb = bias_r[nt][hf];
            *(float2*)&g_xproj[((size_t)t * B_ + r0) * NG + col] =
                make_float2(acc[nt][hf][0] + bb.x, acc[nt][hf][1] + bb.y);
            *(float2*)&g_xproj[((size_t)t * B_ + r0 + 8) * NG + col] =
                make_float2(acc[nt][hf][2] + bb.x, acc[nt][hf][3] + bb.y);
        }
}

// ---------------------------------------------------------------------------
// Persistent recurrent kernel:
//   bg = bid>>5 (4 batch groups, 32 batches), cg = bid&31 (32 col groups).
//   Per-bg group barrier (32 blocks) — dependency-exact.
//   A (h rows) loaded in ONE cp.async burst per step (64KB, no chunking).
// smem: A [2hl][8kt][32m][128B]=64K, B [2hl][64n][1024B]=128K, xs 8.5K, pre 9K.
// ---------------------------------------------------------------------------
#define SMB_A    0
#define SMB_B    65536
#define SMB_XS   196608       // [32 b][272 B] = 8704
#define SMB_PRE  205312       // float[64 n][36 m] = 9216
#define SMB_TOT  214528

__global__ __launch_bounds__(NTHR) void recurrent_kernel(
    const float* __restrict__ Rf, const float* __restrict__ Ri,
    const float* __restrict__ Ro, const float* __restrict__ Rz)
{
    extern __shared__ __align__(1024) char smem[];
    const uint32_t sb = smem_u32(smem);

    const int bid  = blockIdx.x;
    const int tid  = threadIdx.x;
    const int w    = tid >> 5;
    const int lane = tid & 31;
    const int bg   = bid >> 5;       // batch group 0..3 (contiguous SMs)
    const int cg   = bid & 31;       // col group 0..31

    float* xsf = (float*)(smem + SMB_XS);
    float* pre = (float*)(smem + SMB_PRE);

    // stage split R^T slice (once): row n = h_loc*4+g (64 rows), 512 k
    {
        const float* Rm[4] = {Rf, Ri, Ro, Rz};
        for (int idx = tid; idx < 64 * H_; idx += NTHR) {
            int n = idx & 63;
            int k = idx >> 6;
            int hl = n >> 2, g = n & 3;
            float v = Rm[g][(size_t)k * H_ + cg * 16 + hl];
            __nv_bfloat16 vhi = __float2bfloat16(v);
            __nv_bfloat16 vlo = __float2bfloat16(v - __bfloat162float(vhi));
            uint32_t off = n * 1024 + ((((uint32_t)k >> 3) ^ (n & 7)) << 4) + (k & 7) * 2;
            *(__nv_bfloat16*)(smem + SMB_B + off) = vhi;
            *(__nv_bfloat16*)(smem + SMB_B + 65536 + off) = vlo;
        }
    }

    // prefetch xproj[0] slice: 32 b x 64 cols (256B/row -> 272B padded)
    {
#pragma unroll
        for (int e = 0; e < 2; e++) {
            int idx = e * NTHR + tid;
            int b = idx >> 4, u = idx & 15;
            const void* src = g_xproj + (size_t)(bg * 32 + b) * NG + cg * 64 + u * 4;
            cpasync16(sb + SMB_XS + b * 272 + u * 16, src);
        }
        asm volatile("cp.async.commit_group;\n");
    }
    __syncthreads();

    // MMA mapping: wm = w&1 (m-tile of 16), wn = w>>1 (n-tile of 16)
    const int wm = w & 1;
    const int wn = w >> 1;
    const int lrow = lane & 15;
    const int lku  = lane >> 4;
    const uint32_t a_row_off = (uint32_t)((wm * 16 + lrow) * 128);
    const uint32_t a_sw      = (uint32_t)(lrow & 7);
    const uint32_t b_base    = sb + SMB_B + (wn * 16 + lrow) * 1024;
    const uint32_t b_sw      = (uint32_t)(lrow & 7);

    // update mapping: thread -> (batch b_loc, h-col pair 2q,2q+1)
    const int ub = tid >> 3;
    const int uq = tid & 7;
    float c_reg[2] = {0.f, 0.f};
    float n_reg[2] = {0.f, 0.f};

    volatile unsigned* arr = &g_arrive4[bg * 32];
    volatile unsigned* rel = &g_release4[bg * 32];
    unsigned epoch = 0;

    for (int t = 0; t < T_; t++) {
        const int par = t & 1;
        const __nv_bfloat16* __restrict__ hsrc = &g_hbf[par][0][0][0];

        // ---- single-shot A load: all K=512, hi+lo = 64KB (16 x 16B / thread) ----
        {
#pragma unroll
            for (int i = 0; i < 16; i++) {
                int lin = i * NTHR + tid;      // 0..4095
                int hl = lin >> 11;
                int r  = lin & 2047;
                int kt = r >> 8;
                int m  = (r >> 3) & 31;
                int s  = r & 7;
                const __nv_bfloat16* src =
                    hsrc + ((size_t)hl * B_ + bg * 32 + m) * H_ + kt * 64 + s * 8;
                cpasync16(sb + SMB_A + hl * 32768 + kt * 4096 +
                          m * 128 + ((s ^ (m & 7)) << 4), src);
            }
            asm volatile("cp.async.commit_group;\n");
            asm volatile("cp.async.wait_group 0;\n" ::: "memory");
        }
        __syncthreads();

        float acc[2][4] = {};

#pragma unroll
        for (int kt = 0; kt < 8; kt++) {
            const uint32_t abuf = sb + SMB_A + kt * 4096 + a_row_off;
#pragma unroll
            for (int j = 0; j < 4; j++) {
                uint32_t au = (uint32_t)(j * 2 + lku);
                uint32_t bu = (uint32_t)(kt * 8 + j * 2 + lku);
                uint32_t a_hi = abuf + ((au ^ a_sw) << 4);
                uint32_t a_lo = a_hi + 32768;
                uint32_t b_hi = b_base + ((bu ^ b_sw) << 4);
                uint32_t b_lo = b_hi + 65536;

                uint32_t ah[4], al[4], bh[4], bl[4];
                ldsm4(ah, a_hi);
                ldsm4(al, a_lo);
                ldsm4(bh, b_hi);
                ldsm4(bl, b_lo);

                mma16816(acc[0], ah, bh[0], bh[2]);
                mma16816(acc[0], ah, bl[0], bl[2]);
                mma16816(acc[0], al, bh[0], bh[2]);
                mma16816(acc[1], ah, bh[1], bh[3]);
                mma16816(acc[1], ah, bl[1], bl[3]);
                mma16816(acc[1], al, bh[1], bh[3]);
            }
        }

        // epilogue: D fragments -> pre[n][m] (stride 36)
        {
            int row0 = wm * 16 + (lane >> 2);
#pragma unroll
            for (int nt = 0; nt < 2; nt++) {
                int col0 = wn * 16 + nt * 8 + (lane & 3) * 2;
                pre[(col0    ) * 36 + row0    ] = acc[nt][0];
                pre[(col0 + 1) * 36 + row0    ] = acc[nt][1];
                pre[(col0    ) * 36 + row0 + 8] = acc[nt][2];
                pre[(col0 + 1) * 36 + row0 + 8] = acc[nt][3];
            }
        }
        __syncthreads();

        // pointwise sLSTM update
        {
            const int np = par ^ 1;
            const int gb = bg * 32 + ub;
            uint32_t phi, plo;
            __nv_bfloat16* vhi = (__nv_bfloat16*)&phi;
            __nv_bfloat16* vlo = (__nv_bfloat16*)&plo;
#pragma unroll
            for (int e = 0; e < 2; e++) {
                int hc = uq * 2 + e;
                float ft = pre[(hc * 4 + 0) * 36 + ub] + xsf[ub * 68 + hc * 4 + 0];
                float it = pre[(hc * 4 + 1) * 36 + ub] + xsf[ub * 68 + hc * 4 + 1];
                float ot = pre[(hc * 4 + 2) * 36 + ub] + xsf[ub * 68 + hc * 4 + 2];
                float zt = pre[(hc * 4 + 3) * 36 + ub] + xsf[ub * 68 + hc * 4 + 3];

                float o  = __fdividef(1.f, 1.f + __expf(-ot));
                float z  = 1.f - __fdividef(2.f, __expf(2.f * zt) + 1.f);
                float fh = __expf(fminf(ft, 10.f));
                float ih = __expf(fminf(it, 10.f));
                float rd = __fdividef(1.f, fh + ih + 1e-8f);
                float f  = fh * rd;
                float ii = ih * rd;
                c_reg[e] = f * c_reg[e] + ii * z;
                n_reg[e] = f * n_reg[e] + ii;
                float hv = o * __fdividef(c_reg[e], n_reg[e] + 1e-8f);

                vhi[e] = __float2bfloat16(hv);
                vlo[e] = __float2bfloat16(hv - __bfloat162float(vhi[e]));
            }
            *(uint32_t*)&g_hbf[np][0][gb][cg * 16 + uq * 2] = phi;
            *(uint32_t*)&g_hbf[np][1][gb][cg * 16 + uq * 2] = plo;
        }

        __syncthreads();

        // prefetch xproj[t+1] in barrier shadow
        if (t + 1 < T_) {
#pragma unroll
            for (int e = 0; e < 2; e++) {
                int idx = e * NTHR + tid;
                int b = idx >> 4, u = idx & 15;
                const void* src = g_xproj + ((size_t)(t + 1) * B_ + bg * 32 + b) * NG
                                + cg * 64 + u * 4;
                cpasync16(sb + SMB_XS + b * 272 + u * 16, src);
            }
            asm volatile("cp.async.commit_group;\n");
        }

        // ---- per-bg group barrier (32 blocks) ----
        epoch++;
        if (tid == 0) {
            __threadfence();
            unsigned a = atomicAdd((unsigned*)arr, 1u) + 1u;
            if (a == epoch * 32) {
                *rel = epoch;
                __threadfence();
            } else {
                while (*rel < epoch) { }
                __threadfence();
            }
        }
        __syncthreads();
    }

    asm volatile("cp.async.wait_group 0;\n" ::: "memory");
}

// ---------------------------------------------------------------------------
__global__ __launch_bounds__(128) void head_kernel(
    const float* __restrict__ fcw, const float* __restrict__ fcb,
    float* __restrict__ out)
{
    int b = blockIdx.x;
    float s = 0.f;
    for (int k = threadIdx.x; k < H_; k += 128) {
        float hv = __bfloat162float(g_hbf[0][0][b][k]) +
                   __bfloat162float(g_hbf[0][1][b][k]);
        s += hv * fcw[k];
    }

    __shared__ float red[4];
#pragma unroll
    for (int off = 16; off; off >>= 1)
        s += __shfl_down_sync(0xffffffff, s, off);
    if ((threadIdx.x & 31) == 0) red[threadIdx.x >> 5] = s;
    __syncthreads();
    if (threadIdx.x == 0) {
        float tot = red[0] + red[1] + red[2] + red[3];
        out[b] = tanhf(tot + fcb[0]);
    }
}

// ---------------------------------------------------------------------------
extern "C" void kernel_launch(void* const* d_in, const int* in_sizes, int n_in,
                              void* d_out, int out_size)
{
    const float* x   = (const float*)d_in[0];
    const float* Wf  = (const float*)d_in[1];
    const float* bf  = (const float*)d_in[2];
    const float* Wi  = (const float*)d_in[3];
    const float* bi  = (const float*)d_in[4];
    const float* Wo  = (const float*)d_in[5];
    const float* bo  = (const float*)d_in[6];
    const float* Wz  = (const float*)d_in[7];
    const float* bz  = (const float*)d_in[8];
    const float* Rf  = (const float*)d_in[9];
    const float* Ri  = (const float*)d_in[10];
    const float* Ro  = (const float*)d_in[11];
    const float* Rz  = (const float*)d_in[12];
    const float* fcw = (const float*)d_in[13];
    const float* fcb = (const float*)d_in[14];
    float* out = (float*)d_out;

    cudaFuncSetAttribute(recurrent_kernel,
                         cudaFuncAttributeMaxDynamicSharedMemorySize, SMB_TOT);
    cudaFuncSetAttribute(proj_mma_kernel,
                         cudaFuncAttributeMaxDynamicSharedMemorySize, PJ_TOT);

    init_kernel<<<(2 * B_ * H_ + 255) / 256, 256>>>();

    split_x_kernel<<<(B_ * T_ * 32) / 256, 256>>>(x);
    split_w_kernel<<<(NG * 32) / 256, 256>>>(Wf, bf, Wi, bi, Wo, bo, Wz, bz);

    dim3 gP(NG / 64, T_);
    proj_mma_kernel<<<gP, 256, PJ_TOT>>>();

    recurrent_kernel<<<NBLK, NTHR, SMB_TOT>>>(Rf, Ri, Ro, Rz);

    head_kernel<<<B_, 128>>>(fcw, fcb, out);
}

// round 13
// speedup vs baseline: 4.0112x; 1.0363x over previous
#include <cuda_runtime.h>
#include <cuda_bf16.h>
#include <math.h>
#include <stdint.h>

#define B_ 128
#define T_ 512
#define F_ 256
#define H_ 512
#define NG 2048               // H_*4 fused gate cols, n = h*4+g
#define NBLK 128
#define NTHR 256

// ---------------- device globals (allocation-free scratch) ------------------
__device__ float g_xproj[(size_t)T_ * B_ * NG];             // [t][b][n]
__device__ unsigned char g_xs[2][(size_t)B_ * T_ * F_ * 2]; // bf16 hi/lo, pre-swizzled
__device__ unsigned char g_wt[2][(size_t)NG * F_ * 2];      // bf16 hi/lo W^T, pre-swizzled
__device__ float g_bc[NG];                                  // fused bias
__device__ __nv_bfloat16 g_hbf[2][2][B_][H_];               // [parity][hi/lo][b][k]
__device__ volatile unsigned g_arrive4[4 * 32];             // 128B-spaced per-group
__device__ volatile unsigned g_release4[4 * 32];

// ---------------------------------------------------------------------------
__device__ __forceinline__ uint32_t smem_u32(const void* p) {
    uint32_t a;
    asm("{ .reg .u64 t; cvta.to.shared.u64 t, %1; cvt.u32.u64 %0, t; }" : "=r"(a) : "l"(p));
    return a;
}
__device__ __forceinline__ void cpasync16(uint32_t dst_smem, const void* src) {
    asm volatile("cp.async.cg.shared.global [%0], [%1], 16;\n"
                 :: "r"(dst_smem), "l"(src));
}
__device__ __forceinline__ void ldsm4(uint32_t* r, uint32_t addr) {
    asm volatile("ldmatrix.sync.aligned.m8n8.x4.shared.b16 {%0,%1,%2,%3}, [%4];"
                 : "=r"(r[0]), "=r"(r[1]), "=r"(r[2]), "=r"(r[3]) : "r"(addr));
}
__device__ __forceinline__ void mma16816(float* d, const uint32_t* a,
                                         uint32_t b0, uint32_t b1) {
    asm volatile(
        "mma.sync.aligned.m16n8k16.row.col.f32.bf16.bf16.f32 "
        "{%0,%1,%2,%3}, {%4,%5,%6,%7}, {%8,%9}, {%0,%1,%2,%3};"
        : "+f"(d[0]), "+f"(d[1]), "+f"(d[2]), "+f"(d[3])
        : "r"(a[0]), "r"(a[1]), "r"(a[2]), "r"(a[3]), "r"(b0), "r"(b1));
}

// ---------------------------------------------------------------------------
__global__ void init_kernel() {
    int i = blockIdx.x * blockDim.x + threadIdx.x;
    if (i < 2 * B_ * H_) ((__nv_bfloat16*)g_hbf[0])[i] = __float2bfloat16(0.f);
    if (i < 4 * 32) { g_arrive4[i] = 0u; g_release4[i] = 0u; }
}

// ---------------------------------------------------------------------------
__global__ __launch_bounds__(256) void split_x_kernel(const float* __restrict__ x) {
    int idx = blockIdx.x * 256 + threadIdx.x;
    int m = idx >> 5;
    int u = idx & 31;
    float v[8];
    *(float4*)&v[0] = *(const float4*)&x[(size_t)m * F_ + u * 8];
    *(float4*)&v[4] = *(const float4*)&x[(size_t)m * F_ + u * 8 + 4];
    __nv_bfloat16 hi[8], lo[8];
#pragma unroll
    for (int i = 0; i < 8; i++) {
        hi[i] = __float2bfloat16(v[i]);
        lo[i] = __float2bfloat16(v[i] - __bfloat162float(hi[i]));
    }
    int key = (m >> 9) & 7;
    size_t dst = (size_t)m * 512 + ((u ^ key) << 4);
    *(uint4*)(g_xs[0] + dst) = *(uint4*)hi;
    *(uint4*)(g_xs[1] + dst) = *(uint4*)lo;
}

// ---------------------------------------------------------------------------
__global__ __launch_bounds__(256) void split_w_kernel(
    const float* __restrict__ W0, const float* __restrict__ b0v,
    const float* __restrict__ W1, const float* __restrict__ b1v,
    const float* __restrict__ W2, const float* __restrict__ b2v,
    const float* __restrict__ W3, const float* __restrict__ b3v)
{
    int idx = blockIdx.x * 256 + threadIdx.x;
    int n = idx >> 5;
    int u = idx & 31;
    int h = n >> 2, g = n & 3;
    const float* W = (g == 0) ? W0 : (g == 1) ? W1 : (g == 2) ? W2 : W3;
    __nv_bfloat16 hi[8], lo[8];
#pragma unroll
    for (int i = 0; i < 8; i++) {
        float v = W[(size_t)(u * 8 + i) * H_ + h];
        hi[i] = __float2bfloat16(v);
        lo[i] = __float2bfloat16(v - __bfloat162float(hi[i]));
    }
    size_t dst = (size_t)n * 512 + ((u ^ (n & 7)) << 4);
    *(uint4*)(g_wt[0] + dst) = *(uint4*)hi;
    *(uint4*)(g_wt[1] + dst) = *(uint4*)lo;
    if (u == 0) {
        const float* bias = (g == 0) ? b0v : (g == 1) ? b1v : (g == 2) ? b2v : b3v;
        g_bc[n] = bias[h];
    }
}

// ---------------------------------------------------------------------------
// Proj GEMM (tensor) — unchanged.
// ---------------------------------------------------------------------------
#define PJ_A   0
#define PJ_B   65536
#define PJ_TOT 98304

__global__ __launch_bounds__(256) void proj_mma_kernel() {
    extern __shared__ __align__(1024) char smem[];
    const uint32_t sb = smem_u32(smem);

    const int t    = blockIdx.y;
    const int n0   = blockIdx.x * 64;
    const int tid  = threadIdx.x;
    const int w    = tid >> 5;
    const int lane = tid & 31;
    const int lrow = lane & 15;
    const int lku  = lane >> 4;

    float2 bias_r[4][2];
#pragma unroll
    for (int nt = 0; nt < 4; nt++)
#pragma unroll
        for (int hf = 0; hf < 2; hf++) {
            int col = n0 + nt * 16 + hf * 8 + (lane & 3) * 2;
            bias_r[nt][hf] = *(const float2*)&g_bc[col];
        }

    auto load_chunk = [&](int c, int buf) {
#pragma unroll
        for (int i = 0; i < 8; i++) {
            int lin = i * 256 + tid;
            int hl = lin >> 10;
            int r  = lin & 1023;
            int b  = r >> 3;
            int uu = r & 7;
            const void* src = g_xs[hl] + ((size_t)(b * T_ + t) * 512 + c * 128 + uu * 16);
            cpasync16(sb + PJ_A + buf * 32768 + hl * 16384 + b * 128 + uu * 16, src);
        }
#pragma unroll
        for (int i = 0; i < 4; i++) {
            int lin = i * 256 + tid;
            int hl = lin >> 9;
            int r  = lin & 511;
            int nl = r >> 3;
            int uu = r & 7;
            const void* src = g_wt[hl] + ((size_t)(n0 + nl) * 512 + c * 128 + uu * 16);
            cpasync16(sb + PJ_B + buf * 16384 + hl * 8192 + nl * 128 + uu * 16, src);
        }
        asm volatile("cp.async.commit_group;\n");
    };

    load_chunk(0, 0);

    float acc[4][2][4] = {};

    for (int c = 0; c < 4; c++) {
        const int buf = c & 1;
        asm volatile("cp.async.wait_group 0;\n" ::: "memory");
        __syncthreads();
        if (c + 1 < 4) load_chunk(c + 1, buf ^ 1);

        const uint32_t a_base = sb + PJ_A + buf * 32768 + (w * 16 + lrow) * 128;
        const uint32_t b_base = sb + PJ_B + buf * 16384;
        const uint32_t asw = (uint32_t)(lrow & 7);

#pragma unroll
        for (int j = 0; j < 4; j++) {
            uint32_t au = (uint32_t)(j * 2 + lku);
            uint32_t ah[4], al[4];
            ldsm4(ah, a_base + ((au ^ asw) << 4));
            ldsm4(al, a_base + 16384 + ((au ^ asw) << 4));

#pragma unroll
            for (int nt = 0; nt < 4; nt++) {
                uint32_t brow = b_base + (nt * 16 + lrow) * 128;
                uint32_t bh[4], bl[4];
                ldsm4(bh, brow + ((au ^ asw) << 4));
                ldsm4(bl, brow + 8192 + ((au ^ asw) << 4));

                mma16816(acc[nt][0], ah, bh[0], bh[2]);
                mma16816(acc[nt][0], ah, bl[0], bl[2]);
                mma16816(acc[nt][0], al, bh[0], bh[2]);
                mma16816(acc[nt][1], ah, bh[1], bh[3]);
                mma16816(acc[nt][1], ah, bl[1], bl[3]);
                mma16816(acc[nt][1], al, bh[1], bh[3]);
            }
        }
        __syncthreads();
    }

    const int r0 = w * 16 + (lane >> 2);
#pragma unroll
    for (int nt = 0; nt < 4; nt++)
#pragma unroll
        for (int hf = 0; hf < 2; hf++) {
            int col = n0 + nt * 16 + hf * 8 + (lane & 3) * 2;
            float2 bb = bias_r[nt][hf];
            *(float2*)&g_xproj[((size_t)t * B_ + r0) * NG + col] =
                make_float2(acc[nt][hf][0] + bb.x, acc[nt][hf][1] + bb.y);
            *(float2*)&g_xproj[((size_t)t * B_ + r0 + 8) * NG + col] =
                make_float2(acc[nt][hf][2] + bb.x, acc[nt][hf][3] + bb.y);
        }
}

// ---------------------------------------------------------------------------
// Persistent recurrent kernel (R11 base + split-K warp layout):
//   bg = bid>>5, cg = bid&31; per-bg group barrier; single-shot A load.
//   Warp (wn = w&3, wk = w>>2): m = all 32 rows (2 m-tiles), n = wn*16..+16,
//   k = wk*256..+256. Halves reduced via two pre banks in the update phase.
//   Per warp/step: 96 ldsm.x4 + 192 mma (ldsm halved vs R11).
// ---------------------------------------------------------------------------
#define SMB_A    0            // [2 hl][8 kt][32 m][128B] = 65536
#define SMB_B    65536        // [2 hl][64 n][1024 B]     = 131072
#define SMB_XS   196608       // [32 b][272 B] = 8704
#define SMB_PRE  205312       // 2 x float[64 n][36 m] = 18432
#define SMB_TOT  223744

__global__ __launch_bounds__(NTHR) void recurrent_kernel(
    const float* __restrict__ Rf, const float* __restrict__ Ri,
    const float* __restrict__ Ro, const float* __restrict__ Rz)
{
    extern __shared__ __align__(1024) char smem[];
    const uint32_t sb = smem_u32(smem);

    const int bid  = blockIdx.x;
    const int tid  = threadIdx.x;
    const int w    = tid >> 5;
    const int lane = tid & 31;
    const int bg   = bid >> 5;       // batch group 0..3
    const int cg   = bid & 31;       // col group 0..31

    float* xsf = (float*)(smem + SMB_XS);
    float* pre = (float*)(smem + SMB_PRE);   // two banks of 2304 floats

    // stage split R^T slice (once): row n = h_loc*4+g (64 rows), 512 k
    {
        const float* Rm[4] = {Rf, Ri, Ro, Rz};
        for (int idx = tid; idx < 64 * H_; idx += NTHR) {
            int n = idx & 63;
            int k = idx >> 6;
            int hl = n >> 2, g = n & 3;
            float v = Rm[g][(size_t)k * H_ + cg * 16 + hl];
            __nv_bfloat16 vhi = __float2bfloat16(v);
            __nv_bfloat16 vlo = __float2bfloat16(v - __bfloat162float(vhi));
            uint32_t off = n * 1024 + ((((uint32_t)k >> 3) ^ (n & 7)) << 4) + (k & 7) * 2;
            *(__nv_bfloat16*)(smem + SMB_B + off) = vhi;
            *(__nv_bfloat16*)(smem + SMB_B + 65536 + off) = vlo;
        }
    }

    // prefetch xproj[0] slice
    {
#pragma unroll
        for (int e = 0; e < 2; e++) {
            int idx = e * NTHR + tid;
            int b = idx >> 4, u = idx & 15;
            const void* src = g_xproj + (size_t)(bg * 32 + b) * NG + cg * 64 + u * 4;
            cpasync16(sb + SMB_XS + b * 272 + u * 16, src);
        }
        asm volatile("cp.async.commit_group;\n");
    }
    __syncthreads();

    // split-K MMA mapping: wn = n-tile (16 cols), wk = k-half (256 k)
    const int wn = w & 3;
    const int wk = w >> 2;
    const int lrow = lane & 15;
    const int lku  = lane >> 4;
    const uint32_t lsw    = (uint32_t)(lrow & 7);            // swizzle key (rows mod 8)
    const uint32_t a_base = sb + SMB_A + lrow * 128;         // + kt*4096 + mt*2048
    const uint32_t b_base = sb + SMB_B + (wn * 16 + lrow) * 1024;
    float* preh = pre + wk * 2304;

    // update mapping
    const int ub = tid >> 3;
    const int uq = tid & 7;
    float c_reg[2] = {0.f, 0.f};
    float n_reg[2] = {0.f, 0.f};

    volatile unsigned* arr = &g_arrive4[bg * 32];
    volatile unsigned* rel = &g_release4[bg * 32];
    unsigned epoch = 0;

    for (int t = 0; t < T_; t++) {
        const int par = t & 1;
        const __nv_bfloat16* __restrict__ hsrc = &g_hbf[par][0][0][0];

        // ---- single-shot A load: all K=512, hi+lo = 64KB (16 x 16B / thread) ----
        {
#pragma unroll
            for (int i = 0; i < 16; i++) {
                int lin = i * NTHR + tid;      // 0..4095
                int hl = lin >> 11;
                int r  = lin & 2047;
                int kt = r >> 8;
                int m  = (r >> 3) & 31;
                int s  = r & 7;
                const __nv_bfloat16* src =
                    hsrc + ((size_t)hl * B_ + bg * 32 + m) * H_ + kt * 64 + s * 8;
                cpasync16(sb + SMB_A + hl * 32768 + kt * 4096 +
                          m * 128 + ((s ^ (m & 7)) << 4), src);
            }
            asm volatile("cp.async.commit_group;\n");
            asm volatile("cp.async.wait_group 0;\n" ::: "memory");
        }
        __syncthreads();

        float acc[2][2][4] = {};   // [mt][n8][4]

#pragma unroll
        for (int j = 0; j < 16; j++) {
            const int kt = wk * 4 + (j >> 2);
            const uint32_t au = (uint32_t)((j & 3) * 2 + lku);
            const uint32_t bu = (uint32_t)(wk * 32 + j * 2 + lku);

            const uint32_t a_hi0 = a_base + kt * 4096 + ((au ^ lsw) << 4);
            const uint32_t a_hi1 = a_hi0 + 2048;
            const uint32_t b_hi  = b_base + ((bu ^ lsw) << 4);

            uint32_t ah0[4], ah1[4], al0[4], al1[4], bh[4], bl[4];
            ldsm4(ah0, a_hi0);
            ldsm4(ah1, a_hi1);
            ldsm4(al0, a_hi0 + 32768);
            ldsm4(al1, a_hi1 + 32768);
            ldsm4(bh, b_hi);
            ldsm4(bl, b_hi + 65536);

            mma16816(acc[0][0], ah0, bh[0], bh[2]);
            mma16816(acc[0][0], ah0, bl[0], bl[2]);
            mma16816(acc[0][0], al0, bh[0], bh[2]);
            mma16816(acc[0][1], ah0, bh[1], bh[3]);
            mma16816(acc[0][1], ah0, bl[1], bl[3]);
            mma16816(acc[0][1], al0, bh[1], bh[3]);

            mma16816(acc[1][0], ah1, bh[0], bh[2]);
            mma16816(acc[1][0], ah1, bl[0], bl[2]);
            mma16816(acc[1][0], al1, bh[0], bh[2]);
            mma16816(acc[1][1], ah1, bh[1], bh[3]);
            mma16816(acc[1][1], ah1, bl[1], bl[3]);
            mma16816(acc[1][1], al1, bh[1], bh[3]);
        }

        // epilogue: D fragments -> preh[n][m] (bank wk, stride 36)
        {
            int r0 = lane >> 2;
#pragma unroll
            for (int mt = 0; mt < 2; mt++) {
                int row0 = mt * 16 + r0;
#pragma unroll
                for (int n8 = 0; n8 < 2; n8++) {
                    int col0 = wn * 16 + n8 * 8 + (lane & 3) * 2;
                    preh[(col0    ) * 36 + row0    ] = acc[mt][n8][0];
                    preh[(col0 + 1) * 36 + row0    ] = acc[mt][n8][1];
                    preh[(col0    ) * 36 + row0 + 8] = acc[mt][n8][2];
                    preh[(col0 + 1) * 36 + row0 + 8] = acc[mt][n8][3];
                }
            }
        }
        __syncthreads();

        // pointwise sLSTM update (sum the two k-half banks)
        {
            const int np = par ^ 1;
            const int gb = bg * 32 + ub;
            uint32_t phi, plo;
            __nv_bfloat16* vhi = (__nv_bfloat16*)&phi;
            __nv_bfloat16* vlo = (__nv_bfloat16*)&plo;
#pragma unroll
            for (int e = 0; e < 2; e++) {
                int hc = uq * 2 + e;
                float ft = pre[(hc * 4 + 0) * 36 + ub] + pre[2304 + (hc * 4 + 0) * 36 + ub]
                         + xsf[ub * 68 + hc * 4 + 0];
                float it = pre[(hc * 4 + 1) * 36 + ub] + pre[2304 + (hc * 4 + 1) * 36 + ub]
                         + xsf[ub * 68 + hc * 4 + 1];
                float ot = pre[(hc * 4 + 2) * 36 + ub] + pre[2304 + (hc * 4 + 2) * 36 + ub]
                         + xsf[ub * 68 + hc * 4 + 2];
                float zt = pre[(hc * 4 + 3) * 36 + ub] + pre[2304 + (hc * 4 + 3) * 36 + ub]
                         + xsf[ub * 68 + hc * 4 + 3];

                float o  = __fdividef(1.f, 1.f + __expf(-ot));
                float z  = 1.f - __fdividef(2.f, __expf(2.f * zt) + 1.f);
                float fh = __expf(fminf(ft, 10.f));
                float ih = __expf(fminf(it, 10.f));
                float rd = __fdividef(1.f, fh + ih + 1e-8f);
                float f  = fh * rd;
                float ii = ih * rd;
                c_reg[e] = f * c_reg[e] + ii * z;
                n_reg[e] = f * n_reg[e] + ii;
                float hv = o * __fdividef(c_reg[e], n_reg[e] + 1e-8f);

                vhi[e] = __float2bfloat16(hv);
                vlo[e] = __float2bfloat16(hv - __bfloat162float(vhi[e]));
            }
            *(uint32_t*)&g_hbf[np][0][gb][cg * 16 + uq * 2] = phi;
            *(uint32_t*)&g_hbf[np][1][gb][cg * 16 + uq * 2] = plo;
        }

        __syncthreads();

        // prefetch xproj[t+1] in barrier shadow
        if (t + 1 < T_) {
#pragma unroll
            for (int e = 0; e < 2; e++) {
                int idx = e * NTHR + tid;
                int b = idx >> 4, u = idx & 15;
                const void* src = g_xproj + ((size_t)(t + 1) * B_ + bg * 32 + b) * NG
                                + cg * 64 + u * 4;
                cpasync16(sb + SMB_XS + b * 272 + u * 16, src);
            }
            asm volatile("cp.async.commit_group;\n");
        }

        // ---- per-bg group barrier (32 blocks) ----
        epoch++;
        if (tid == 0) {
            __threadfence();
            unsigned a = atomicAdd((unsigned*)arr, 1u) + 1u;
            if (a == epoch * 32) {
                *rel = epoch;
                __threadfence();
            } else {
                while (*rel < epoch) { }
                __threadfence();
            }
        }
        __syncthreads();
    }

    asm volatile("cp.async.wait_group 0;\n" ::: "memory");
}

// ---------------------------------------------------------------------------
__global__ __launch_bounds__(128) void head_kernel(
    const float* __restrict__ fcw, const float* __restrict__ fcb,
    float* __restrict__ out)
{
    int b = blockIdx.x;
    float s = 0.f;
    for (int k = threadIdx.x; k < H_; k += 128) {
        float hv = __bfloat162float(g_hbf[0][0][b][k]) +
                   __bfloat162float(g_hbf[0][1][b][k]);
        s += hv * fcw[k];
    }

    __shared__ float red[4];
#pragma unroll
    for (int off = 16; off; off >>= 1)
        s += __shfl_down_sync(0xffffffff, s, off);
    if ((threadIdx.x & 31) == 0) red[threadIdx.x >> 5] = s;
    __syncthreads();
    if (threadIdx.x == 0) {
        float tot = red[0] + red[1] + red[2] + red[3];
        out[b] = tanhf(tot + fcb[0]);
    }
}

// ---------------------------------------------------------------------------
extern "C" void kernel_launch(void* const* d_in, const int* in_sizes, int n_in,
                              void* d_out, int out_size)
{
    const float* x   = (const float*)d_in[0];
    const float* Wf  = (const float*)d_in[1];
    const float* bf  = (const float*)d_in[2];
    const float* Wi  = (const float*)d_in[3];
    const float* bi  = (const float*)d_in[4];
    const float* Wo  = (const float*)d_in[5];
    const float* bo  = (const float*)d_in[6];
    const float* Wz  = (const float*)d_in[7];
    const float* bz  = (const float*)d_in[8];
    const float* Rf  = (const float*)d_in[9];
    const float* Ri  = (const float*)d_in[10];
    const float* Ro  = (const float*)d_in[11];
    const float* Rz  = (const float*)d_in[12];
    const float* fcw = (const float*)d_in[13];
    const float* fcb = (const float*)d_in[14];
    float* out = (float*)d_out;

    cudaFuncSetAttribute(recurrent_kernel,
                         cudaFuncAttributeMaxDynamicSharedMemorySize, SMB_TOT);
    cudaFuncSetAttribute(proj_mma_kernel,
                         cudaFuncAttributeMaxDynamicSharedMemorySize, PJ_TOT);

    init_kernel<<<(2 * B_ * H_ + 255) / 256, 256>>>();

    split_x_kernel<<<(B_ * T_ * 32) / 256, 256>>>(x);
    split_w_kernel<<<(NG * 32) / 256, 256>>>(Wf, bf, Wi, bi, Wo, bo, Wz, bz);

    dim3 gP(NG / 64, T_);
    proj_mma_kernel<<<gP, 256, PJ_TOT>>>();

    recurrent_kernel<<<NBLK, NTHR, SMB_TOT>>>(Rf, Ri, Ro, Rz);

    head_kernel<<<B_, 128>>>(fcw, fcb, out);
}